// round 13
// baseline (speedup 1.0000x reference)
#include <cuda_runtime.h>
#include <cuda_fp16.h>
#include <math.h>
#include <stdint.h>

#define BN   65536
#define DZ   32
#define HIDN 512
#define DXN  256
#define PHN  5
#define LOG2PI 1.8378770664093453f

// ===================== helpers =====================
__device__ __forceinline__ uint32_t smem_u32(const void* p) {
    uint32_t a;
    asm("{ .reg .u64 t; cvta.to.shared.u64 t, %1; cvt.u32.u64 %0, t; }" : "=r"(a) : "l"(p));
    return a;
}

__device__ __forceinline__ void mma_f16(float& d0, float& d1, float& d2, float& d3,
                                        uint32_t a0, uint32_t a1, uint32_t a2, uint32_t a3,
                                        uint32_t b0, uint32_t b1) {
    asm volatile("mma.sync.aligned.m16n8k16.row.col.f32.f16.f16.f32 "
                 "{%0,%1,%2,%3},{%4,%5,%6,%7},{%8,%9},{%0,%1,%2,%3};"
                 : "+f"(d0), "+f"(d1), "+f"(d2), "+f"(d3)
                 : "r"(a0), "r"(a1), "r"(a2), "r"(a3), "r"(b0), "r"(b1));
}

// fp16 round-to-nearest split: x = hi + lo, both packed f16x2 (low half = x0)
__device__ __forceinline__ void split2h(float x0, float x1, uint32_t& hi, uint32_t& lo) {
    asm("cvt.rn.f16x2.f32 %0, %1, %2;" : "=r"(hi) : "f"(x1), "f"(x0));
    __half2 h = *reinterpret_cast<__half2*>(&hi);
    float f0 = __half2float(__low2half(h));
    float f1 = __half2float(__high2half(h));
    float l0 = x0 - f0, l1 = x1 - f1;
    asm("cvt.rn.f16x2.f32 %0, %1, %2;" : "=r"(lo) : "f"(l1), "f"(l0));
}

__device__ __forceinline__ uint32_t pack2h(float x0, float x1) {
    uint32_t r;
    asm("cvt.rn.f16x2.f32 %0, %1, %2;" : "=r"(r) : "f"(x1), "f"(x0));
    return r;
}

__device__ __forceinline__ void ldmx4(uint32_t* r, uint32_t addr) {
    asm volatile("ldmatrix.sync.aligned.m8n8.x4.shared.b16 {%0,%1,%2,%3}, [%4];"
                 : "=r"(r[0]), "=r"(r[1]), "=r"(r[2]), "=r"(r[3]) : "r"(addr));
}

__device__ __forceinline__ void cp16(uint32_t dst, const void* src) {
    asm volatile("cp.async.cg.shared.global [%0], [%1], 16;" :: "r"(dst), "l"(src));
}
#define CP_COMMIT() asm volatile("cp.async.commit_group;" ::: "memory")
#define CP_WAIT0()  asm volatile("cp.async.wait_group 0;" ::: "memory")

// ===================== global scratch =====================
__device__ float g_per_node[DZ];
__device__ float g_sum_e1;
__device__ int   g_active_mask;

__device__ uint32_t gW1f[16 * 1024];     // 64 KB  fp16 hi/lo fragments
__device__ uint32_t gW2f[16 * 4096];     // 256 KB fp16 single fragments

// ===================== prep kernels =====================
__global__ void prep_w1f(const float* __restrict__ Wd1) {
    int idx = blockIdx.x * 256 + threadIdx.x;
    if (idx >= 4096) return;
    int lane = idx & 31, nt = (idx >> 5) & 3, kt = (idx >> 7) & 1, kc = idx >> 8;
    int t = lane & 3, g = lane >> 2;
    int k0 = kt * 16 + t * 2;
    int n  = kc * 32 + nt * 8 + g;
    float b00 = Wd1[(k0    ) * HIDN + n];
    float b01 = Wd1[(k0 + 1) * HIDN + n];
    float b10 = Wd1[(k0 + 8) * HIDN + n];
    float b11 = Wd1[(k0 + 9) * HIDN + n];
    uint32_t hi0, lo0, hi1, lo1;
    split2h(b00, b01, hi0, lo0);
    split2h(b10, b11, hi1, lo1);
    uint32_t* p = gW1f + (((kc * 2 + kt) * 4 + nt) * 32 + lane) * 4;
    p[0] = hi0; p[1] = hi1; p[2] = lo0; p[3] = lo1;
}

__global__ void prep_w2f(const float* __restrict__ Wd2) {
    int idx = blockIdx.x * 256 + threadIdx.x;      // 0..16383
    if (idx >= 16384) return;
    int lane = idx & 31, nf = (idx >> 5) & 31, kc = idx >> 10;
    int t = lane & 3, g = lane >> 2;
    int k0 = kc * 32 + t * 2;
    int n  = nf * 8 + g;
    uint32_t q[4];
    #pragma unroll
    for (int j = 0; j < 4; ++j) {
        int kk = k0 + j * 8;
        q[j] = pack2h(Wd2[kk * DXN + n], Wd2[(kk + 1) * DXN + n]);
    }
    uint32_t* p = gW2f + ((kc * 32 + nf) * 32 + lane) * 4;
    p[0] = q[0]; p[1] = q[1]; p[2] = q[2]; p[3] = q[3];
}

// ===================== fused decoder + flow =====================
#define SMEM_W2   0                      /* 2 x 32768 (big chunk) */
#define SMEM_W1   65536                  /* 65536 */
#define SMEM_BD1  131072                 /* 2048 */
#define SMEM_EH   133120                 /* 10240 */
#define SMEM_EL   143360                 /* 10240 */
#define SMEM_H    153600                 /* 2 x 20480 (hi only, two subs) */
// flow weight staging (used by es==0 CTAs only)
#define FL_W1M    194560                 /* 20480: [n][k][d] masked */
#define FL_W2     215040                 /* 3200:  [n][m][k] */
#define FL_B1     218240                 /* 640 */
#define FL_B2     218880                 /* 640 */
#define FL_W3     219520                 /* 1280:  [n][r][m] */
#define FL_B3     220800                 /* 256:   [n][r] */
#define FL_RED    221056                 /* 33 floats */
#define SMEM_TOT  221440

// GEMM1 (3-term fp16) for 32-sub-chunk kcn -> H at byte offset hoff.
__device__ __forceinline__ void gemm1_chunk(char* sm, uint32_t sb, int kcn, uint32_t hoff,
                                            int w, int lane, int t, int g)
{
    const int mt8 = w >> 1, nh = w & 1;
    const char* w1s = sm + SMEM_W1 + kcn * 4096;
    const float* bd1s = (const float*)(sm + SMEM_BD1) + kcn * 32;
    char* hbase = sm + hoff;

    const uint32_t arow = (uint32_t)((mt8 * 16 + (lane & 15)) * 80 + (lane >> 4) * 16);
    const uint32_t ehb = sb + SMEM_EH + arow;
    const uint32_t elb = sb + SMEM_EL + arow;

    float ha[2][4];
    #pragma unroll
    for (int ntl = 0; ntl < 2; ++ntl)
        #pragma unroll
        for (int r = 0; r < 4; ++r) ha[ntl][r] = 0.0f;

    #pragma unroll
    for (int kt = 0; kt < 2; ++kt) {
        uint32_t eh[4], el[4];
        ldmx4(eh, ehb + kt * 32);
        ldmx4(el, elb + kt * 32);
        #pragma unroll
        for (int ntl = 0; ntl < 2; ++ntl) {
            const int ntg = nh * 2 + ntl;
            uint4 bf = *reinterpret_cast<const uint4*>(
                w1s + (kt * 4 + ntg) * 512 + lane * 16);
            mma_f16(ha[ntl][0], ha[ntl][1], ha[ntl][2], ha[ntl][3],
                    eh[0], eh[1], eh[2], eh[3], bf.x, bf.y);
            mma_f16(ha[ntl][0], ha[ntl][1], ha[ntl][2], ha[ntl][3],
                    eh[0], eh[1], eh[2], eh[3], bf.z, bf.w);
            mma_f16(ha[ntl][0], ha[ntl][1], ha[ntl][2], ha[ntl][3],
                    el[0], el[1], el[2], el[3], bf.x, bf.y);
        }
    }

    const int rowA = mt8 * 16 + g;
    #pragma unroll
    for (int ntl = 0; ntl < 2; ++ntl) {
        const int col = nh * 16 + ntl * 8 + t * 2;
        float2 bb = *reinterpret_cast<const float2*>(bd1s + col);
        float c0 = fmaxf(ha[ntl][0] + bb.x, 0.0f);
        float c1 = fmaxf(ha[ntl][1] + bb.y, 0.0f);
        float c2 = fmaxf(ha[ntl][2] + bb.x, 0.0f);
        float c3 = fmaxf(ha[ntl][3] + bb.y, 0.0f);
        const uint32_t offA = (uint32_t)(rowA * 80 + (col >> 1) * 4);
        *reinterpret_cast<uint32_t*>(hbase + offA)       = pack2h(c0, c1);
        *reinterpret_cast<uint32_t*>(hbase + offA + 640) = pack2h(c2, c3);  // row +8
    }
}

// GEMM2: s/nf-outer, mf-inner; each B fragment loaded ONCE per sub-chunk.
__device__ __forceinline__ void gemm2_big(const char* sm, uint32_t hb0, int kc,
                                          int wn, int lane, float (&acc)[2][8][4])
{
    const char* w2b = sm + SMEM_W2 + (kc & 1) * 32768;
    const uint32_t hhb = hb0 + (kc & 1) * 20480;
    #pragma unroll
    for (int s = 0; s < 2; ++s) {
        const char* w2s = w2b + s * 16384;
        const uint32_t hh = hhb + s * 10240;
        uint32_t hf[2][2][4];
        #pragma unroll
        for (int mf = 0; mf < 2; ++mf) {
            ldmx4(hf[mf][0], hh + mf * (16 * 80));
            ldmx4(hf[mf][1], hh + mf * (16 * 80) + 32);
        }
        #pragma unroll
        for (int nf = 0; nf < 8; ++nf) {
            uint4 bf = *reinterpret_cast<const uint4*>(
                w2s + (wn * 8 + nf) * 512 + lane * 16);
            #pragma unroll
            for (int mf = 0; mf < 2; ++mf) {
                mma_f16(acc[mf][nf][0], acc[mf][nf][1], acc[mf][nf][2], acc[mf][nf][3],
                        hf[mf][0][0], hf[mf][0][1], hf[mf][0][2], hf[mf][0][3], bf.x, bf.y);
                mma_f16(acc[mf][nf][0], acc[mf][nf][1], acc[mf][nf][2], acc[mf][nf][3],
                        hf[mf][1][0], hf[mf][1][1], hf[mf][1][2], hf[mf][1][3], bf.z, bf.w);
            }
        }
    }
}

__global__ __launch_bounds__(512, 1)
void dec_mma(const float* __restrict__ e1, const float* __restrict__ e2,
             const float* __restrict__ bd1, const float* __restrict__ bd2,
             const float* __restrict__ adj,
             const float* __restrict__ W1, const float* __restrict__ b1,
             const float* __restrict__ W2, const float* __restrict__ b2,
             const float* __restrict__ W3, const float* __restrict__ b3,
             float* __restrict__ out)
{
    extern __shared__ char sm[];
    const uint32_t sb = smem_u32(sm);
    const int tid = threadIdx.x, lane = tid & 31, w = tid >> 5;
    const int t = lane & 3, g = lane >> 2;
    const int mt = blockIdx.x, es = blockIdx.y;
    const float* E = es ? e2 : e1;
    const int wm = w & 3, wn = w >> 2;
    const int row0 = mt * 128 + wm * 32;

    // stage bd1 (512 floats)
    ((float*)(sm + SMEM_BD1))[tid] = bd1[tid];

    // stage E tile split hi/lo (fp16)
    {
        const int row = tid >> 2, seg = tid & 3;
        const float4* src = reinterpret_cast<const float4*>(
            E + (size_t)(mt * 128 + row) * DZ + seg * 8);
        float4 v0 = src[0], v1 = src[1];
        uint32_t hibuf[4], lobuf[4];
        split2h(v0.x, v0.y, hibuf[0], lobuf[0]);
        split2h(v0.z, v0.w, hibuf[1], lobuf[1]);
        split2h(v1.x, v1.y, hibuf[2], lobuf[2]);
        split2h(v1.z, v1.w, hibuf[3], lobuf[3]);
        *reinterpret_cast<uint4*>(sm + SMEM_EH + row * 80 + seg * 16) =
            *reinterpret_cast<uint4*>(hibuf);
        *reinterpret_cast<uint4*>(sm + SMEM_EL + row * 80 + seg * 16) =
            *reinterpret_cast<uint4*>(lobuf);
    }

    // preload ALL W1 (64 KB) + W2 big chunk 0 (32 KB)
    {
        const uint4* g1 = reinterpret_cast<const uint4*>(gW1f);
        #pragma unroll
        for (int q = 0; q < 8; ++q)
            cp16(sb + SMEM_W1 + (tid + 512 * q) * 16, g1 + tid + 512 * q);
        const uint4* g2 = reinterpret_cast<const uint4*>(gW2f);
        #pragma unroll
        for (int q = 0; q < 4; ++q)
            cp16(sb + SMEM_W2 + (tid + 512 * q) * 16, g2 + tid + 512 * q);
        CP_COMMIT();
    }

    // stage flow weights (es==0 CTAs only); separate smem region, overlaps cp.async
    if (es == 0) {
        float* fw1 = (float*)(sm + FL_W1M);
        for (int idx = tid; idx < DZ * PHN * DZ; idx += 512) {
            int n = idx / (PHN * DZ);
            int d = idx & (DZ - 1);
            float m = 0.0f;
            if (d < n)      m = 1.0f / (1.0f + expf(-adj[d * DZ + n]));
            else if (d > n) m = 1.0f - 1.0f / (1.0f + expf(-adj[n * DZ + d]));
            fw1[idx] = m * W1[idx];
        }
        float* fw2 = (float*)(sm + FL_W2);
        for (int idx = tid; idx < DZ * PHN * PHN; idx += 512) fw2[idx] = W2[idx];
        if (tid < DZ * PHN) {
            ((float*)(sm + FL_B1))[tid] = b1[tid];
            ((float*)(sm + FL_B2))[tid] = b2[tid];
        }
        float* fw3 = (float*)(sm + FL_W3);
        for (int idx = tid; idx < DZ * 2 * PHN; idx += 512) {
            int n = idx / (2 * PHN); int rem = idx - n * 2 * PHN;
            fw3[idx] = W3[n * DZ * PHN + rem];
        }
        if (tid < DZ * 2) ((float*)(sm + FL_B3))[tid] = b3[(tid >> 1) * DZ + (tid & 1)];
        if (tid < 33) ((float*)(sm + FL_RED))[tid] = 0.0f;
    }

    float acc[2][8][4];
    #pragma unroll
    for (int mf = 0; mf < 2; ++mf)
        #pragma unroll
        for (int nf = 0; nf < 8; ++nf)
            #pragma unroll
            for (int r = 0; r < 4; ++r) acc[mf][nf][r] = 0.0f;

    const uint32_t lm_off = (uint32_t)((wm * 32 + (lane & 15)) * 80 + (lane >> 4) * 16);
    const uint32_t hb0 = sb + SMEM_H + lm_off;

    CP_WAIT0();
    __syncthreads();
    gemm1_chunk(sm, sb, 0, SMEM_H,         w, lane, t, g);
    gemm1_chunk(sm, sb, 1, SMEM_H + 10240, w, lane, t, g);
    __syncthreads();

    for (int kc = 0; kc < 8; ++kc) {
        if (kc + 1 < 8) {
            const uint4* g2 = reinterpret_cast<const uint4*>(gW2f + (kc + 1) * 8192);
            const uint32_t dst = sb + SMEM_W2 + ((kc + 1) & 1) * 32768;
            #pragma unroll
            for (int q = 0; q < 4; ++q)
                cp16(dst + (tid + 512 * q) * 16, g2 + tid + 512 * q);
            CP_COMMIT();
        }

        const uint32_t hoff = SMEM_H + ((kc + 1) & 1) * 20480;
        if (w & 1) {
            gemm2_big(sm, hb0, kc, wn, lane, acc);
            if (kc + 1 < 8) {
                gemm1_chunk(sm, sb, 2 * (kc + 1),     hoff,         w, lane, t, g);
                gemm1_chunk(sm, sb, 2 * (kc + 1) + 1, hoff + 10240, w, lane, t, g);
            }
        } else {
            if (kc + 1 < 8) {
                gemm1_chunk(sm, sb, 2 * (kc + 1),     hoff,         w, lane, t, g);
                gemm1_chunk(sm, sb, 2 * (kc + 1) + 1, hoff + 10240, w, lane, t, g);
            }
            gemm2_big(sm, hb0, kc, wn, lane, acc);
        }

        CP_WAIT0();
        __syncthreads();
    }

    // ---- epilogue2: + bd2, store ----
    float* o = out + (size_t)es * BN * DXN;
    #pragma unroll
    for (int mf = 0; mf < 2; ++mf) {
        const int ra = row0 + mf * 16 + g;
        const int rb = ra + 8;
        #pragma unroll
        for (int nf = 0; nf < 8; ++nf) {
            const int cb = wn * 64 + nf * 8 + t * 2;
            float2 bb = *reinterpret_cast<const float2*>(bd2 + cb);
            float2 o0 = make_float2(acc[mf][nf][0] + bb.x, acc[mf][nf][1] + bb.y);
            float2 o1 = make_float2(acc[mf][nf][2] + bb.x, acc[mf][nf][3] + bb.y);
            *reinterpret_cast<float2*>(o + (size_t)ra * DXN + cb) = o0;
            *reinterpret_cast<float2*>(o + (size_t)rb * DXN + cb) = o1;
        }
    }

    // ---- flow tail (es==0 only): 4 threads per row, 8 nodes per thread ----
    if (es == 0) {
        const int frow = tid >> 2, slice = tid & 3;
        const int gr = mt * 128 + frow;
        float x[DZ];
        #pragma unroll
        for (int q = 0; q < 8; ++q) {
            float4 v = *reinterpret_cast<const float4*>(e1 + (size_t)gr * DZ + 4 * q);
            x[4*q] = v.x; x[4*q+1] = v.y; x[4*q+2] = v.z; x[4*q+3] = v.w;
        }
        float se1 = 0.0f;
        #pragma unroll
        for (int d = 0; d < 8; ++d) { float xv = x[slice * 8 + d]; se1 += xv * xv; }
        se1 *= -0.5f;

        float e2v[8];
        {
            float4 a = *reinterpret_cast<const float4*>(e2 + (size_t)gr * DZ + slice * 8);
            float4 b = *reinterpret_cast<const float4*>(e2 + (size_t)gr * DZ + slice * 8 + 4);
            e2v[0]=a.x; e2v[1]=a.y; e2v[2]=a.z; e2v[3]=a.w;
            e2v[4]=b.x; e2v[5]=b.y; e2v[6]=b.z; e2v[7]=b.w;
        }

        const float* fb1 = (const float*)(sm + FL_B1);
        const float* fb2 = (const float*)(sm + FL_B2);
        const float* fb3 = (const float*)(sm + FL_B3);
        float pn[8];
        #pragma unroll 1
        for (int nl = 0; nl < 8; ++nl) {
            const int n = slice * 8 + nl;
            const float* w1p = (const float*)(sm + FL_W1M) + n * PHN * DZ;
            float h1[PHN];
            #pragma unroll
            for (int k = 0; k < PHN; ++k) {
                const float4* wv = reinterpret_cast<const float4*>(w1p + k * DZ);
                float s = fb1[n * PHN + k];
                #pragma unroll
                for (int q = 0; q < 8; ++q) {
                    float4 v = wv[q];
                    s += x[4*q] * v.x + x[4*q+1] * v.y + x[4*q+2] * v.z + x[4*q+3] * v.w;
                }
                h1[k] = fmaxf(s, 0.0f);
            }
            const float* w2p = (const float*)(sm + FL_W2) + n * PHN * PHN;
            float h2[PHN];
            #pragma unroll
            for (int m = 0; m < PHN; ++m) {
                float s = fb2[n * PHN + m];
                #pragma unroll
                for (int k = 0; k < PHN; ++k) s += h1[k] * w2p[m * PHN + k];
                h2[m] = fmaxf(s, 0.0f);
            }
            const float* w3p = (const float*)(sm + FL_W3) + n * 2 * PHN;
            float shift = fb3[2 * n], lsc = fb3[2 * n + 1];
            #pragma unroll
            for (int m = 0; m < PHN; ++m) { shift += h2[m] * w3p[m]; lsc += h2[m] * w3p[PHN + m]; }
            float z = (e2v[nl] - shift) * expf(-lsc);
            pn[nl] = -0.5f * z * z - lsc;
        }

        // reduce over the warp's 8 rows (lanes differing in bits 2..4)
        #pragma unroll
        for (int o = 16; o >= 4; o >>= 1) {
            se1 += __shfl_xor_sync(0xffffffffu, se1, o);
            #pragma unroll
            for (int nl = 0; nl < 8; ++nl)
                pn[nl] += __shfl_xor_sync(0xffffffffu, pn[nl], o);
        }
        // se1: also reduce across slices
        se1 += __shfl_xor_sync(0xffffffffu, se1, 2);
        se1 += __shfl_xor_sync(0xffffffffu, se1, 1);

        float* red = (float*)(sm + FL_RED);
        if (lane < 4) {
            #pragma unroll
            for (int nl = 0; nl < 8; ++nl)
                atomicAdd(&red[lane * 8 + nl], pn[nl]);
        }
        if (lane == 0) atomicAdd(&red[32], se1);
        __syncthreads();
        if (tid < DZ) atomicAdd(&g_per_node[tid], red[tid]);
        if (tid == DZ) atomicAdd(&g_sum_e1, red[32]);
    }
}

// ===================== small kernels =====================
__global__ void init_kernel() {
    int t = threadIdx.x;
    if (t < DZ) g_per_node[t] = 0.0f;
    if (t == DZ) { g_sum_e1 = 0.0f; g_active_mask = 0; }
}

__global__ void active_kernel(const int* __restrict__ itv) {
    const int n4 = (BN * (DZ + 1)) / 4;
    unsigned mask = 0;
    const int stride = gridDim.x * blockDim.x;
    for (int i = blockIdx.x * blockDim.x + threadIdx.x; i < n4; i += stride) {
        int4 v = reinterpret_cast<const int4*>(itv)[i];
        int c0 = (4 * i) % 33;
        int c1 = (c0 + 1 == 33) ? 0 : c0 + 1;
        int c2 = (c1 + 1 == 33) ? 0 : c1 + 1;
        int c3 = (c2 + 1 == 33) ? 0 : c2 + 1;
        if (v.x && c0) mask |= 1u << (c0 - 1);
        if (v.y && c1) mask |= 1u << (c1 - 1);
        if (v.z && c2) mask |= 1u << (c2 - 1);
        if (v.w && c3) mask |= 1u << (c3 - 1);
    }
    mask = __reduce_or_sync(0xffffffffu, mask);
    if ((threadIdx.x & 31) == 0 && mask) atomicOr(&g_active_mask, (int)mask);
}

__global__ void finalize_kernel(float* __restrict__ out) {
    if (threadIdx.x == 0 && blockIdx.x == 0) {
        float lp = g_sum_e1 - 0.5f * LOG2PI * (float)((long long)BN * DZ);
        int msk = g_active_mask;
        #pragma unroll
        for (int n = 0; n < DZ; ++n)
            if ((msk >> n) & 1) lp += g_per_node[n] - 0.5f * LOG2PI * (float)BN;
        lp -= logf((float)(DZ + 1)) * (float)BN;
        out[(size_t)2 * BN * DXN] = lp;
    }
}

// ===================== kernel_launch =====================
extern "C" void kernel_launch(void* const* d_in, const int* in_sizes, int n_in,
                              void* d_out, int out_size)
{
    (void)in_sizes; (void)n_in; (void)out_size;
    const float* e1  = (const float*)d_in[0];
    const float* e2  = (const float*)d_in[1];
    const float* adj = (const float*)d_in[2];
    const float* W1  = (const float*)d_in[3];
    const float* b1  = (const float*)d_in[4];
    const float* W2  = (const float*)d_in[5];
    const float* b2  = (const float*)d_in[6];
    const float* W3  = (const float*)d_in[7];
    const float* b3  = (const float*)d_in[8];
    const float* Wd1 = (const float*)d_in[9];
    const float* bd1 = (const float*)d_in[10];
    const float* Wd2 = (const float*)d_in[11];
    const float* bd2 = (const float*)d_in[12];
    const int*   itv = (const int*)d_in[13];
    float* out = (float*)d_out;

    cudaFuncSetAttribute(dec_mma, cudaFuncAttributeMaxDynamicSharedMemorySize, SMEM_TOT);

    init_kernel<<<1, 64>>>();
    prep_w1f<<<16, 256>>>(Wd1);
    prep_w2f<<<64, 256>>>(Wd2);
    dim3 dg(BN / 128, 2);
    dec_mma<<<dg, 512, SMEM_TOT>>>(e1, e2, bd1, bd2, adj, W1, b1, W2, b2, W3, b3, out);
    active_kernel<<<264, 256>>>(itv);
    finalize_kernel<<<1, 32>>>(out);
}

// round 14
// speedup vs baseline: 1.4867x; 1.4867x over previous
#include <cuda_runtime.h>
#include <cuda_fp16.h>
#include <math.h>
#include <stdint.h>

#define BN   65536
#define DZ   32
#define HIDN 512
#define DXN  256
#define PHN  5
#define LOG2PI 1.8378770664093453f

// ===================== helpers =====================
__device__ __forceinline__ uint32_t smem_u32(const void* p) {
    uint32_t a;
    asm("{ .reg .u64 t; cvta.to.shared.u64 t, %1; cvt.u32.u64 %0, t; }" : "=r"(a) : "l"(p));
    return a;
}

__device__ __forceinline__ void mma_f16(float& d0, float& d1, float& d2, float& d3,
                                        uint32_t a0, uint32_t a1, uint32_t a2, uint32_t a3,
                                        uint32_t b0, uint32_t b1) {
    asm volatile("mma.sync.aligned.m16n8k16.row.col.f32.f16.f16.f32 "
                 "{%0,%1,%2,%3},{%4,%5,%6,%7},{%8,%9},{%0,%1,%2,%3};"
                 : "+f"(d0), "+f"(d1), "+f"(d2), "+f"(d3)
                 : "r"(a0), "r"(a1), "r"(a2), "r"(a3), "r"(b0), "r"(b1));
}

// fp16 round-to-nearest split: x = hi + lo, both packed f16x2 (low half = x0)
__device__ __forceinline__ void split2h(float x0, float x1, uint32_t& hi, uint32_t& lo) {
    asm("cvt.rn.f16x2.f32 %0, %1, %2;" : "=r"(hi) : "f"(x1), "f"(x0));
    __half2 h = *reinterpret_cast<__half2*>(&hi);
    float f0 = __half2float(__low2half(h));
    float f1 = __half2float(__high2half(h));
    float l0 = x0 - f0, l1 = x1 - f1;
    asm("cvt.rn.f16x2.f32 %0, %1, %2;" : "=r"(lo) : "f"(l1), "f"(l0));
}

__device__ __forceinline__ uint32_t pack2h(float x0, float x1) {
    uint32_t r;
    asm("cvt.rn.f16x2.f32 %0, %1, %2;" : "=r"(r) : "f"(x1), "f"(x0));
    return r;
}

__device__ __forceinline__ void ldmx4(uint32_t* r, uint32_t addr) {
    asm volatile("ldmatrix.sync.aligned.m8n8.x4.shared.b16 {%0,%1,%2,%3}, [%4];"
                 : "=r"(r[0]), "=r"(r[1]), "=r"(r[2]), "=r"(r[3]) : "r"(addr));
}

__device__ __forceinline__ void cp16(uint32_t dst, const void* src) {
    asm volatile("cp.async.cg.shared.global [%0], [%1], 16;" :: "r"(dst), "l"(src));
}
#define CP_COMMIT() asm volatile("cp.async.commit_group;" ::: "memory")
#define CP_WAIT0()  asm volatile("cp.async.wait_group 0;" ::: "memory")

// ===================== global scratch =====================
__device__ float g_per_node[DZ];
__device__ float g_sum_e1;
__device__ int   g_active_mask;

__device__ uint32_t gW1f[16 * 1024];     // 64 KB  fp16 hi/lo fragments
__device__ uint32_t gW2f[16 * 4096];     // 256 KB fp16 single fragments

// ===================== prep kernels =====================
__global__ void prep_w1f(const float* __restrict__ Wd1) {
    int idx = blockIdx.x * 256 + threadIdx.x;
    if (idx >= 4096) return;
    int lane = idx & 31, nt = (idx >> 5) & 3, kt = (idx >> 7) & 1, kc = idx >> 8;
    int t = lane & 3, g = lane >> 2;
    int k0 = kt * 16 + t * 2;
    int n  = kc * 32 + nt * 8 + g;
    float b00 = Wd1[(k0    ) * HIDN + n];
    float b01 = Wd1[(k0 + 1) * HIDN + n];
    float b10 = Wd1[(k0 + 8) * HIDN + n];
    float b11 = Wd1[(k0 + 9) * HIDN + n];
    uint32_t hi0, lo0, hi1, lo1;
    split2h(b00, b01, hi0, lo0);
    split2h(b10, b11, hi1, lo1);
    uint32_t* p = gW1f + (((kc * 2 + kt) * 4 + nt) * 32 + lane) * 4;
    p[0] = hi0; p[1] = hi1; p[2] = lo0; p[3] = lo1;
}

__global__ void prep_w2f(const float* __restrict__ Wd2) {
    int idx = blockIdx.x * 256 + threadIdx.x;      // 0..16383
    if (idx >= 16384) return;
    int lane = idx & 31, nf = (idx >> 5) & 31, kc = idx >> 10;
    int t = lane & 3, g = lane >> 2;
    int k0 = kc * 32 + t * 2;
    int n  = nf * 8 + g;
    uint32_t q[4];
    #pragma unroll
    for (int j = 0; j < 4; ++j) {
        int kk = k0 + j * 8;
        q[j] = pack2h(Wd2[kk * DXN + n], Wd2[(kk + 1) * DXN + n]);
    }
    uint32_t* p = gW2f + ((kc * 32 + nf) * 32 + lane) * 4;
    p[0] = q[0]; p[1] = q[1]; p[2] = q[2]; p[3] = q[3];
}

// ===================== fused decoder =====================
// CTA: 128 rows x 256 cols; 16 warps = 4(m) x 4(n) for GEMM2 (warp tile 32x64).
// Big K-chunk = 64 (two 32-sub-chunks per barrier).
// fp16: GEMM1 exact 3-term; H and W2 single rounded fp16 in GEMM2.
#define SMEM_W2   0                      /* 2 x 32768 (big chunk) */
#define SMEM_W1   65536                  /* 65536 */
#define SMEM_BD1  131072                 /* 2048 */
#define SMEM_EH   133120                 /* 10240 */
#define SMEM_EL   143360                 /* 10240 */
#define SMEM_H    153600                 /* 2 x 20480 (hi only, two subs) */
#define SMEM_TOT  194560

// GEMM1 (3-term fp16) for 32-sub-chunk kcn -> H at byte offset hoff.
// Warp w: rows [(w>>1)*16, +16), sub-chunk cols [(w&1)*16, +16).
__device__ __forceinline__ void gemm1_chunk(char* sm, uint32_t sb, int kcn, uint32_t hoff,
                                            int w, int lane, int t, int g)
{
    const int mt8 = w >> 1, nh = w & 1;
    const char* w1s = sm + SMEM_W1 + kcn * 4096;
    const float* bd1s = (const float*)(sm + SMEM_BD1) + kcn * 32;
    char* hbase = sm + hoff;

    const uint32_t arow = (uint32_t)((mt8 * 16 + (lane & 15)) * 80 + (lane >> 4) * 16);
    const uint32_t ehb = sb + SMEM_EH + arow;
    const uint32_t elb = sb + SMEM_EL + arow;

    float ha[2][4];
    #pragma unroll
    for (int ntl = 0; ntl < 2; ++ntl)
        #pragma unroll
        for (int r = 0; r < 4; ++r) ha[ntl][r] = 0.0f;

    #pragma unroll
    for (int kt = 0; kt < 2; ++kt) {
        uint32_t eh[4], el[4];
        ldmx4(eh, ehb + kt * 32);
        ldmx4(el, elb + kt * 32);
        #pragma unroll
        for (int ntl = 0; ntl < 2; ++ntl) {
            const int ntg = nh * 2 + ntl;
            uint4 bf = *reinterpret_cast<const uint4*>(
                w1s + (kt * 4 + ntg) * 512 + lane * 16);
            mma_f16(ha[ntl][0], ha[ntl][1], ha[ntl][2], ha[ntl][3],
                    eh[0], eh[1], eh[2], eh[3], bf.x, bf.y);
            mma_f16(ha[ntl][0], ha[ntl][1], ha[ntl][2], ha[ntl][3],
                    eh[0], eh[1], eh[2], eh[3], bf.z, bf.w);
            mma_f16(ha[ntl][0], ha[ntl][1], ha[ntl][2], ha[ntl][3],
                    el[0], el[1], el[2], el[3], bf.x, bf.y);
        }
    }

    const int rowA = mt8 * 16 + g;
    #pragma unroll
    for (int ntl = 0; ntl < 2; ++ntl) {
        const int col = nh * 16 + ntl * 8 + t * 2;
        float2 bb = *reinterpret_cast<const float2*>(bd1s + col);
        float c0 = fmaxf(ha[ntl][0] + bb.x, 0.0f);
        float c1 = fmaxf(ha[ntl][1] + bb.y, 0.0f);
        float c2 = fmaxf(ha[ntl][2] + bb.x, 0.0f);
        float c3 = fmaxf(ha[ntl][3] + bb.y, 0.0f);
        const uint32_t offA = (uint32_t)(rowA * 80 + (col >> 1) * 4);
        *reinterpret_cast<uint32_t*>(hbase + offA)       = pack2h(c0, c1);
        *reinterpret_cast<uint32_t*>(hbase + offA + 640) = pack2h(c2, c3);  // row +8
    }
}

// GEMM2: s-outer, B fragment loaded ONCE per sub-chunk (both mf share it).
__device__ __forceinline__ void gemm2_big(const char* sm, uint32_t hb0, int kc,
                                          int wn, int lane, float (&acc)[2][8][4])
{
    const char* w2b = sm + SMEM_W2 + (kc & 1) * 32768;
    const uint32_t hhb = hb0 + (kc & 1) * 20480;
    #pragma unroll
    for (int s = 0; s < 2; ++s) {
        const char* w2s = w2b + s * 16384;
        const uint32_t hh = hhb + s * 10240;
        uint32_t hf[2][2][4];
        #pragma unroll
        for (int mf = 0; mf < 2; ++mf) {
            ldmx4(hf[mf][0], hh + mf * (16 * 80));
            ldmx4(hf[mf][1], hh + mf * (16 * 80) + 32);
        }
        #pragma unroll
        for (int nf = 0; nf < 8; ++nf) {
            uint4 bf = *reinterpret_cast<const uint4*>(
                w2s + (wn * 8 + nf) * 512 + lane * 16);
            #pragma unroll
            for (int mf = 0; mf < 2; ++mf) {
                mma_f16(acc[mf][nf][0], acc[mf][nf][1], acc[mf][nf][2], acc[mf][nf][3],
                        hf[mf][0][0], hf[mf][0][1], hf[mf][0][2], hf[mf][0][3], bf.x, bf.y);
                mma_f16(acc[mf][nf][0], acc[mf][nf][1], acc[mf][nf][2], acc[mf][nf][3],
                        hf[mf][1][0], hf[mf][1][1], hf[mf][1][2], hf[mf][1][3], bf.z, bf.w);
            }
        }
    }
}

__global__ __launch_bounds__(512, 1)
void dec_mma(const float* __restrict__ e1, const float* __restrict__ e2,
             const float* __restrict__ bd1, const float* __restrict__ bd2,
             float* __restrict__ out)
{
    extern __shared__ char sm[];
    const uint32_t sb = smem_u32(sm);
    const int tid = threadIdx.x, lane = tid & 31, w = tid >> 5;
    const int t = lane & 3, g = lane >> 2;
    const int mt = blockIdx.x, es = blockIdx.y;
    const float* E = es ? e2 : e1;
    const int wm = w & 3, wn = w >> 2;
    const int row0 = mt * 128 + wm * 32;

    // stage bd1 (512 floats)
    ((float*)(sm + SMEM_BD1))[tid] = bd1[tid];

    // stage E tile split hi/lo (fp16): row = tid>>2, 8 cols per thread
    {
        const int row = tid >> 2, seg = tid & 3;
        const float4* src = reinterpret_cast<const float4*>(
            E + (size_t)(mt * 128 + row) * DZ + seg * 8);
        float4 v0 = src[0], v1 = src[1];
        uint32_t hibuf[4], lobuf[4];
        split2h(v0.x, v0.y, hibuf[0], lobuf[0]);
        split2h(v0.z, v0.w, hibuf[1], lobuf[1]);
        split2h(v1.x, v1.y, hibuf[2], lobuf[2]);
        split2h(v1.z, v1.w, hibuf[3], lobuf[3]);
        *reinterpret_cast<uint4*>(sm + SMEM_EH + row * 80 + seg * 16) =
            *reinterpret_cast<uint4*>(hibuf);
        *reinterpret_cast<uint4*>(sm + SMEM_EL + row * 80 + seg * 16) =
            *reinterpret_cast<uint4*>(lobuf);
    }

    // preload ALL W1 (64 KB) + W2 big chunk 0 (32 KB)
    {
        const uint4* g1 = reinterpret_cast<const uint4*>(gW1f);
        #pragma unroll
        for (int q = 0; q < 8; ++q)
            cp16(sb + SMEM_W1 + (tid + 512 * q) * 16, g1 + tid + 512 * q);
        const uint4* g2 = reinterpret_cast<const uint4*>(gW2f);
        #pragma unroll
        for (int q = 0; q < 4; ++q)
            cp16(sb + SMEM_W2 + (tid + 512 * q) * 16, g2 + tid + 512 * q);
        CP_COMMIT();
    }

    float acc[2][8][4];
    #pragma unroll
    for (int mf = 0; mf < 2; ++mf)
        #pragma unroll
        for (int nf = 0; nf < 8; ++nf)
            #pragma unroll
            for (int r = 0; r < 4; ++r) acc[mf][nf][r] = 0.0f;

    const uint32_t lm_off = (uint32_t)((wm * 32 + (lane & 15)) * 80 + (lane >> 4) * 16);
    const uint32_t hb0 = sb + SMEM_H + lm_off;

    CP_WAIT0();
    __syncthreads();
    gemm1_chunk(sm, sb, 0, SMEM_H,         w, lane, t, g);
    gemm1_chunk(sm, sb, 1, SMEM_H + 10240, w, lane, t, g);
    __syncthreads();

    for (int kc = 0; kc < 8; ++kc) {
        if (kc + 1 < 8) {
            const uint4* g2 = reinterpret_cast<const uint4*>(gW2f + (kc + 1) * 8192);
            const uint32_t dst = sb + SMEM_W2 + ((kc + 1) & 1) * 32768;
            #pragma unroll
            for (int q = 0; q < 4; ++q)
                cp16(dst + (tid + 512 * q) * 16, g2 + tid + 512 * q);
            CP_COMMIT();
        }

        const uint32_t hoff = SMEM_H + ((kc + 1) & 1) * 20480;
        if (w & 1) {
            gemm2_big(sm, hb0, kc, wn, lane, acc);
            if (kc + 1 < 8) {
                gemm1_chunk(sm, sb, 2 * (kc + 1),     hoff,         w, lane, t, g);
                gemm1_chunk(sm, sb, 2 * (kc + 1) + 1, hoff + 10240, w, lane, t, g);
            }
        } else {
            if (kc + 1 < 8) {
                gemm1_chunk(sm, sb, 2 * (kc + 1),     hoff,         w, lane, t, g);
                gemm1_chunk(sm, sb, 2 * (kc + 1) + 1, hoff + 10240, w, lane, t, g);
            }
            gemm2_big(sm, hb0, kc, wn, lane, acc);
        }

        CP_WAIT0();
        __syncthreads();
    }

    // ---- epilogue2: + bd2, store ----
    float* o = out + (size_t)es * BN * DXN;
    #pragma unroll
    for (int mf = 0; mf < 2; ++mf) {
        const int ra = row0 + mf * 16 + g;
        const int rb = ra + 8;
        #pragma unroll
        for (int nf = 0; nf < 8; ++nf) {
            const int cb = wn * 64 + nf * 8 + t * 2;
            float2 bb = *reinterpret_cast<const float2*>(bd2 + cb);
            float2 o0 = make_float2(acc[mf][nf][0] + bb.x, acc[mf][nf][1] + bb.y);
            float2 o1 = make_float2(acc[mf][nf][2] + bb.x, acc[mf][nf][3] + bb.y);
            *reinterpret_cast<float2*>(o + (size_t)ra * DXN + cb) = o0;
            *reinterpret_cast<float2*>(o + (size_t)rb * DXN + cb) = o1;
        }
    }
}

// ===================== flow kernel (2 threads per row) =====================
__global__ __launch_bounds__(256)
void flow_kernel(const float* __restrict__ e1, const float* __restrict__ e2,
                 const float* __restrict__ adj,
                 const float* __restrict__ W1, const float* __restrict__ b1,
                 const float* __restrict__ W2, const float* __restrict__ b2,
                 const float* __restrict__ W3, const float* __restrict__ b3)
{
    __shared__ float Ms[DZ * DZ];
    __shared__ float W1m[DZ * PHN * DZ];
    __shared__ float W2s[DZ * PHN * PHN];
    __shared__ float b1s[DZ * PHN];
    __shared__ float b2s[DZ * PHN];
    __shared__ float W3s[DZ * 2 * PHN];
    __shared__ float b3s[DZ * 2];
    __shared__ float red[DZ];
    __shared__ float rede1;

    const int tid = threadIdx.x;

    for (int idx = tid; idx < DZ * DZ; idx += 256) {
        int i = idx >> 5, j = idx & 31;
        float v = 0.0f;
        if (j < i)      v = 1.0f / (1.0f + expf(-adj[j * DZ + i]));
        else if (j > i) v = 1.0f - 1.0f / (1.0f + expf(-adj[i * DZ + j]));
        Ms[idx] = v;
    }
    for (int idx = tid; idx < DZ * PHN; idx += 256) { b1s[idx] = b1[idx]; b2s[idx] = b2[idx]; }
    for (int idx = tid; idx < DZ * PHN * PHN; idx += 256) W2s[idx] = W2[idx];
    for (int idx = tid; idx < DZ * 2 * PHN; idx += 256) {
        int n = idx / (2 * PHN); int rem = idx - n * 2 * PHN;
        W3s[idx] = W3[n * DZ * PHN + rem];
    }
    for (int idx = tid; idx < DZ * 2; idx += 256)
        b3s[idx] = b3[(idx >> 1) * DZ + (idx & 1)];
    if (tid < DZ) red[tid] = 0.0f;
    if (tid == 0) rede1 = 0.0f;
    __syncthreads();
    for (int idx = tid; idx < DZ * PHN * DZ; idx += 256) {
        int n = idx / (PHN * DZ);
        int d = idx & (DZ - 1);
        W1m[idx] = Ms[n * DZ + d] * W1[idx];
    }
    __syncthreads();

    // 2 threads per batch row: half = tid&1 handles nodes [half*16, +16)
    const int rowl = tid >> 1, half = tid & 1;
    const int b = blockIdx.x * 128 + rowl;
    float x[DZ];
    float se1 = 0.0f;
    #pragma unroll
    for (int q = 0; q < 8; ++q) {
        float4 v = *reinterpret_cast<const float4*>(e1 + (size_t)b * DZ + 4 * q);
        x[4*q] = v.x; x[4*q+1] = v.y; x[4*q+2] = v.z; x[4*q+3] = v.w;
        se1 += v.x*v.x + v.y*v.y + v.z*v.z + v.w*v.w;
    }
    se1 *= -0.5f;

    float e2v[16];
    {
        const float4* e2p = reinterpret_cast<const float4*>(e2 + (size_t)b * DZ + half * 16);
        #pragma unroll
        for (int q = 0; q < 4; ++q) {
            float4 v = e2p[q];
            e2v[4*q] = v.x; e2v[4*q+1] = v.y; e2v[4*q+2] = v.z; e2v[4*q+3] = v.w;
        }
    }

    #pragma unroll 1
    for (int nl = 0; nl < 16; ++nl) {
        const int n = half * 16 + nl;
        const float* w1 = W1m + n * PHN * DZ;
        float h1[PHN];
        #pragma unroll
        for (int k = 0; k < PHN; ++k) {
            const float4* wv = reinterpret_cast<const float4*>(w1 + k * DZ);
            float s = b1s[n * PHN + k];
            #pragma unroll
            for (int q = 0; q < 8; ++q) {
                float4 v = wv[q];
                s += x[4*q] * v.x + x[4*q+1] * v.y + x[4*q+2] * v.z + x[4*q+3] * v.w;
            }
            h1[k] = fmaxf(s, 0.0f);
        }
        const float* w2 = W2s + n * PHN * PHN;
        float h2[PHN];
        #pragma unroll
        for (int m = 0; m < PHN; ++m) {
            float s = b2s[n * PHN + m];
            #pragma unroll
            for (int k = 0; k < PHN; ++k) s += h1[k] * w2[m * PHN + k];
            h2[m] = fmaxf(s, 0.0f);
        }
        const float* w3 = W3s + n * 2 * PHN;
        float shift = b3s[2 * n], lsc = b3s[2 * n + 1];
        #pragma unroll
        for (int m = 0; m < PHN; ++m) { shift += h2[m] * w3[m]; lsc += h2[m] * w3[PHN + m]; }

        float z = (e2v[nl] - shift) * expf(-lsc);
        float c = -0.5f * z * z - lsc;
        // reduce over the warp's 16 rows (lanes differ in bits 1..4; bit 0 = half)
        #pragma unroll
        for (int o = 16; o >= 2; o >>= 1) c += __shfl_xor_sync(0xffffffffu, c, o);
        if ((tid & 31) < 2) atomicAdd(&red[n], c);
    }

    // se1 over full warp (both halves computed the same row-sums; divide by 2)
    #pragma unroll
    for (int o = 16; o; o >>= 1) se1 += __shfl_xor_sync(0xffffffffu, se1, o);
    if ((tid & 31) == 0) atomicAdd(&rede1, 0.5f * se1);
    __syncthreads();
    if (tid < DZ) atomicAdd(&g_per_node[tid], red[tid]);
    if (tid == 0) atomicAdd(&g_sum_e1, rede1);
}

// ===================== small kernels =====================
__global__ void init_kernel() {
    int t = threadIdx.x;
    if (t < DZ) g_per_node[t] = 0.0f;
    if (t == DZ) { g_sum_e1 = 0.0f; g_active_mask = 0; }
}

__global__ void active_kernel(const int* __restrict__ itv) {
    const int n4 = (BN * (DZ + 1)) / 4;
    unsigned mask = 0;
    const int stride = gridDim.x * blockDim.x;
    for (int i = blockIdx.x * blockDim.x + threadIdx.x; i < n4; i += stride) {
        int4 v = reinterpret_cast<const int4*>(itv)[i];
        int c0 = (4 * i) % 33;
        int c1 = (c0 + 1 == 33) ? 0 : c0 + 1;
        int c2 = (c1 + 1 == 33) ? 0 : c1 + 1;
        int c3 = (c2 + 1 == 33) ? 0 : c2 + 1;
        if (v.x && c0) mask |= 1u << (c0 - 1);
        if (v.y && c1) mask |= 1u << (c1 - 1);
        if (v.z && c2) mask |= 1u << (c2 - 1);
        if (v.w && c3) mask |= 1u << (c3 - 1);
    }
    mask = __reduce_or_sync(0xffffffffu, mask);
    if ((threadIdx.x & 31) == 0 && mask) atomicOr(&g_active_mask, (int)mask);
}

__global__ void finalize_kernel(float* __restrict__ out) {
    if (threadIdx.x == 0 && blockIdx.x == 0) {
        float lp = g_sum_e1 - 0.5f * LOG2PI * (float)((long long)BN * DZ);
        int msk = g_active_mask;
        #pragma unroll
        for (int n = 0; n < DZ; ++n)
            if ((msk >> n) & 1) lp += g_per_node[n] - 0.5f * LOG2PI * (float)BN;
        lp -= logf((float)(DZ + 1)) * (float)BN;
        out[(size_t)2 * BN * DXN] = lp;
    }
}

// ===================== kernel_launch =====================
extern "C" void kernel_launch(void* const* d_in, const int* in_sizes, int n_in,
                              void* d_out, int out_size)
{
    (void)in_sizes; (void)n_in; (void)out_size;
    const float* e1  = (const float*)d_in[0];
    const float* e2  = (const float*)d_in[1];
    const float* adj = (const float*)d_in[2];
    const float* W1  = (const float*)d_in[3];
    const float* b1  = (const float*)d_in[4];
    const float* W2  = (const float*)d_in[5];
    const float* b2  = (const float*)d_in[6];
    const float* W3  = (const float*)d_in[7];
    const float* b3  = (const float*)d_in[8];
    const float* Wd1 = (const float*)d_in[9];
    const float* bd1 = (const float*)d_in[10];
    const float* Wd2 = (const float*)d_in[11];
    const float* bd2 = (const float*)d_in[12];
    const int*   itv = (const int*)d_in[13];
    float* out = (float*)d_out;

    cudaFuncSetAttribute(dec_mma, cudaFuncAttributeMaxDynamicSharedMemorySize, SMEM_TOT);

    init_kernel<<<1, 64>>>();
    prep_w1f<<<16, 256>>>(Wd1);
    prep_w2f<<<64, 256>>>(Wd2);
    dim3 dg(BN / 128, 2);
    dec_mma<<<dg, 512, SMEM_TOT>>>(e1, e2, bd1, bd2, out);
    flow_kernel<<<BN / 128, 256>>>(e1, e2, adj, W1, b1, W2, b2, W3, b3);
    active_kernel<<<264, 256>>>(itv);
    finalize_kernel<<<1, 32>>>(out);
}

// round 15
// speedup vs baseline: 1.6979x; 1.1421x over previous
#include <cuda_runtime.h>
#include <cuda_fp16.h>
#include <math.h>
#include <stdint.h>

#define BN   65536
#define DZ   32
#define HIDN 512
#define DXN  256
#define PHN  5
#define LOG2PI 1.8378770664093453f

// ===================== helpers =====================
__device__ __forceinline__ uint32_t smem_u32(const void* p) {
    uint32_t a;
    asm("{ .reg .u64 t; cvta.to.shared.u64 t, %1; cvt.u32.u64 %0, t; }" : "=r"(a) : "l"(p));
    return a;
}

__device__ __forceinline__ void mma_f16(float& d0, float& d1, float& d2, float& d3,
                                        uint32_t a0, uint32_t a1, uint32_t a2, uint32_t a3,
                                        uint32_t b0, uint32_t b1) {
    asm volatile("mma.sync.aligned.m16n8k16.row.col.f32.f16.f16.f32 "
                 "{%0,%1,%2,%3},{%4,%5,%6,%7},{%8,%9},{%0,%1,%2,%3};"
                 : "+f"(d0), "+f"(d1), "+f"(d2), "+f"(d3)
                 : "r"(a0), "r"(a1), "r"(a2), "r"(a3), "r"(b0), "r"(b1));
}

// fp16 round-to-nearest split: x = hi + lo, both packed f16x2 (low half = x0)
__device__ __forceinline__ void split2h(float x0, float x1, uint32_t& hi, uint32_t& lo) {
    asm("cvt.rn.f16x2.f32 %0, %1, %2;" : "=r"(hi) : "f"(x1), "f"(x0));
    __half2 h = *reinterpret_cast<__half2*>(&hi);
    float f0 = __half2float(__low2half(h));
    float f1 = __half2float(__high2half(h));
    float l0 = x0 - f0, l1 = x1 - f1;
    asm("cvt.rn.f16x2.f32 %0, %1, %2;" : "=r"(lo) : "f"(l1), "f"(l0));
}

__device__ __forceinline__ uint32_t pack2h(float x0, float x1) {
    uint32_t r;
    asm("cvt.rn.f16x2.f32 %0, %1, %2;" : "=r"(r) : "f"(x1), "f"(x0));
    return r;
}

__device__ __forceinline__ void ldmx4(uint32_t* r, uint32_t addr) {
    asm volatile("ldmatrix.sync.aligned.m8n8.x4.shared.b16 {%0,%1,%2,%3}, [%4];"
                 : "=r"(r[0]), "=r"(r[1]), "=r"(r[2]), "=r"(r[3]) : "r"(addr));
}

__device__ __forceinline__ void cp16(uint32_t dst, const void* src) {
    asm volatile("cp.async.cg.shared.global [%0], [%1], 16;" :: "r"(dst), "l"(src));
}
#define CP_COMMIT() asm volatile("cp.async.commit_group;" ::: "memory")
#define CP_WAIT0()  asm volatile("cp.async.wait_group 0;" ::: "memory")

// ===================== global scratch =====================
__device__ float g_per_node[DZ];
__device__ float g_sum_e1;
__device__ int   g_active_mask;

__device__ uint32_t gW1f[16 * 1024];     // 64 KB  fp16 hi/lo fragments
__device__ uint32_t gW2f[16 * 4096];     // 256 KB fp16 single fragments

// ===================== prep kernels =====================
__global__ void prep_w1f(const float* __restrict__ Wd1) {
    int idx = blockIdx.x * 256 + threadIdx.x;
    if (idx >= 4096) return;
    int lane = idx & 31, nt = (idx >> 5) & 3, kt = (idx >> 7) & 1, kc = idx >> 8;
    int t = lane & 3, g = lane >> 2;
    int k0 = kt * 16 + t * 2;
    int n  = kc * 32 + nt * 8 + g;
    float b00 = Wd1[(k0    ) * HIDN + n];
    float b01 = Wd1[(k0 + 1) * HIDN + n];
    float b10 = Wd1[(k0 + 8) * HIDN + n];
    float b11 = Wd1[(k0 + 9) * HIDN + n];
    uint32_t hi0, lo0, hi1, lo1;
    split2h(b00, b01, hi0, lo0);
    split2h(b10, b11, hi1, lo1);
    uint32_t* p = gW1f + (((kc * 2 + kt) * 4 + nt) * 32 + lane) * 4;
    p[0] = hi0; p[1] = hi1; p[2] = lo0; p[3] = lo1;
}

__global__ void prep_w2f(const float* __restrict__ Wd2) {
    int idx = blockIdx.x * 256 + threadIdx.x;      // 0..16383
    if (idx >= 16384) return;
    int lane = idx & 31, nf = (idx >> 5) & 31, kc = idx >> 10;
    int t = lane & 3, g = lane >> 2;
    int k0 = kc * 32 + t * 2;
    int n  = nf * 8 + g;
    uint32_t q[4];
    #pragma unroll
    for (int j = 0; j < 4; ++j) {
        int kk = k0 + j * 8;
        q[j] = pack2h(Wd2[kk * DXN + n], Wd2[(kk + 1) * DXN + n]);
    }
    uint32_t* p = gW2f + ((kc * 32 + nf) * 32 + lane) * 4;
    p[0] = q[0]; p[1] = q[1]; p[2] = q[2]; p[3] = q[3];
}

// ===================== fused decoder =====================
#define SMEM_W2   0                      /* 2 x 32768 (big chunk) */
#define SMEM_W1   65536                  /* 65536 */
#define SMEM_BD1  131072                 /* 2048 */
#define SMEM_EH   133120                 /* 10240 */
#define SMEM_EL   143360                 /* 10240 */
#define SMEM_H    153600                 /* 2 x 20480 (hi only, two subs) */
#define SMEM_TOT  194560

// GEMM1 (3-term fp16) for 32-sub-chunk kcn -> H at byte offset hoff.
__device__ __forceinline__ void gemm1_chunk(char* sm, uint32_t sb, int kcn, uint32_t hoff,
                                            int w, int lane, int t, int g)
{
    const int mt8 = w >> 1, nh = w & 1;
    const char* w1s = sm + SMEM_W1 + kcn * 4096;
    const float* bd1s = (const float*)(sm + SMEM_BD1) + kcn * 32;
    char* hbase = sm + hoff;

    const uint32_t arow = (uint32_t)((mt8 * 16 + (lane & 15)) * 80 + (lane >> 4) * 16);
    const uint32_t ehb = sb + SMEM_EH + arow;
    const uint32_t elb = sb + SMEM_EL + arow;

    float ha[2][4];
    #pragma unroll
    for (int ntl = 0; ntl < 2; ++ntl)
        #pragma unroll
        for (int r = 0; r < 4; ++r) ha[ntl][r] = 0.0f;

    #pragma unroll
    for (int kt = 0; kt < 2; ++kt) {
        uint32_t eh[4], el[4];
        ldmx4(eh, ehb + kt * 32);
        ldmx4(el, elb + kt * 32);
        #pragma unroll
        for (int ntl = 0; ntl < 2; ++ntl) {
            const int ntg = nh * 2 + ntl;
            uint4 bf = *reinterpret_cast<const uint4*>(
                w1s + (kt * 4 + ntg) * 512 + lane * 16);
            mma_f16(ha[ntl][0], ha[ntl][1], ha[ntl][2], ha[ntl][3],
                    eh[0], eh[1], eh[2], eh[3], bf.x, bf.y);
            mma_f16(ha[ntl][0], ha[ntl][1], ha[ntl][2], ha[ntl][3],
                    eh[0], eh[1], eh[2], eh[3], bf.z, bf.w);
            mma_f16(ha[ntl][0], ha[ntl][1], ha[ntl][2], ha[ntl][3],
                    el[0], el[1], el[2], el[3], bf.x, bf.y);
        }
    }

    const int rowA = mt8 * 16 + g;
    #pragma unroll
    for (int ntl = 0; ntl < 2; ++ntl) {
        const int col = nh * 16 + ntl * 8 + t * 2;
        float2 bb = *reinterpret_cast<const float2*>(bd1s + col);
        float c0 = fmaxf(ha[ntl][0] + bb.x, 0.0f);
        float c1 = fmaxf(ha[ntl][1] + bb.y, 0.0f);
        float c2 = fmaxf(ha[ntl][2] + bb.x, 0.0f);
        float c3 = fmaxf(ha[ntl][3] + bb.y, 0.0f);
        const uint32_t offA = (uint32_t)(rowA * 80 + (col >> 1) * 4);
        *reinterpret_cast<uint32_t*>(hbase + offA)       = pack2h(c0, c1);
        *reinterpret_cast<uint32_t*>(hbase + offA + 640) = pack2h(c2, c3);  // row +8
    }
}

// GEMM2: s-outer, B fragment loaded ONCE per sub-chunk (both mf share it).
__device__ __forceinline__ void gemm2_big(const char* sm, uint32_t hb0, int kc,
                                          int wn, int lane, float (&acc)[2][8][4])
{
    const char* w2b = sm + SMEM_W2 + (kc & 1) * 32768;
    const uint32_t hhb = hb0 + (kc & 1) * 20480;
    #pragma unroll
    for (int s = 0; s < 2; ++s) {
        const char* w2s = w2b + s * 16384;
        const uint32_t hh = hhb + s * 10240;
        uint32_t hf[2][2][4];
        #pragma unroll
        for (int mf = 0; mf < 2; ++mf) {
            ldmx4(hf[mf][0], hh + mf * (16 * 80));
            ldmx4(hf[mf][1], hh + mf * (16 * 80) + 32);
        }
        #pragma unroll
        for (int nf = 0; nf < 8; ++nf) {
            uint4 bf = *reinterpret_cast<const uint4*>(
                w2s + (wn * 8 + nf) * 512 + lane * 16);
            #pragma unroll
            for (int mf = 0; mf < 2; ++mf) {
                mma_f16(acc[mf][nf][0], acc[mf][nf][1], acc[mf][nf][2], acc[mf][nf][3],
                        hf[mf][0][0], hf[mf][0][1], hf[mf][0][2], hf[mf][0][3], bf.x, bf.y);
                mma_f16(acc[mf][nf][0], acc[mf][nf][1], acc[mf][nf][2], acc[mf][nf][3],
                        hf[mf][1][0], hf[mf][1][1], hf[mf][1][2], hf[mf][1][3], bf.z, bf.w);
            }
        }
    }
}

__global__ __launch_bounds__(512, 1)
void dec_mma(const float* __restrict__ e1, const float* __restrict__ e2,
             const float* __restrict__ bd1, const float* __restrict__ bd2,
             float* __restrict__ out)
{
    extern __shared__ char sm[];
    const uint32_t sb = smem_u32(sm);
    const int tid = threadIdx.x, lane = tid & 31, w = tid >> 5;
    const int t = lane & 3, g = lane >> 2;
    const int mt = blockIdx.x, es = blockIdx.y;
    const float* E = es ? e2 : e1;
    const int wm = w & 3, wn = w >> 2;
    const int row0 = mt * 128 + wm * 32;

    ((float*)(sm + SMEM_BD1))[tid] = bd1[tid];

    {
        const int row = tid >> 2, seg = tid & 3;
        const float4* src = reinterpret_cast<const float4*>(
            E + (size_t)(mt * 128 + row) * DZ + seg * 8);
        float4 v0 = src[0], v1 = src[1];
        uint32_t hibuf[4], lobuf[4];
        split2h(v0.x, v0.y, hibuf[0], lobuf[0]);
        split2h(v0.z, v0.w, hibuf[1], lobuf[1]);
        split2h(v1.x, v1.y, hibuf[2], lobuf[2]);
        split2h(v1.z, v1.w, hibuf[3], lobuf[3]);
        *reinterpret_cast<uint4*>(sm + SMEM_EH + row * 80 + seg * 16) =
            *reinterpret_cast<uint4*>(hibuf);
        *reinterpret_cast<uint4*>(sm + SMEM_EL + row * 80 + seg * 16) =
            *reinterpret_cast<uint4*>(lobuf);
    }

    {
        const uint4* g1 = reinterpret_cast<const uint4*>(gW1f);
        #pragma unroll
        for (int q = 0; q < 8; ++q)
            cp16(sb + SMEM_W1 + (tid + 512 * q) * 16, g1 + tid + 512 * q);
        const uint4* g2 = reinterpret_cast<const uint4*>(gW2f);
        #pragma unroll
        for (int q = 0; q < 4; ++q)
            cp16(sb + SMEM_W2 + (tid + 512 * q) * 16, g2 + tid + 512 * q);
        CP_COMMIT();
    }

    float acc[2][8][4];
    #pragma unroll
    for (int mf = 0; mf < 2; ++mf)
        #pragma unroll
        for (int nf = 0; nf < 8; ++nf)
            #pragma unroll
            for (int r = 0; r < 4; ++r) acc[mf][nf][r] = 0.0f;

    const uint32_t lm_off = (uint32_t)((wm * 32 + (lane & 15)) * 80 + (lane >> 4) * 16);
    const uint32_t hb0 = sb + SMEM_H + lm_off;

    CP_WAIT0();
    __syncthreads();
    gemm1_chunk(sm, sb, 0, SMEM_H,         w, lane, t, g);
    gemm1_chunk(sm, sb, 1, SMEM_H + 10240, w, lane, t, g);
    __syncthreads();

    for (int kc = 0; kc < 8; ++kc) {
        if (kc + 1 < 8) {
            const uint4* g2 = reinterpret_cast<const uint4*>(gW2f + (kc + 1) * 8192);
            const uint32_t dst = sb + SMEM_W2 + ((kc + 1) & 1) * 32768;
            #pragma unroll
            for (int q = 0; q < 4; ++q)
                cp16(dst + (tid + 512 * q) * 16, g2 + tid + 512 * q);
            CP_COMMIT();
        }

        const uint32_t hoff = SMEM_H + ((kc + 1) & 1) * 20480;
        if (w & 1) {
            gemm2_big(sm, hb0, kc, wn, lane, acc);
            if (kc + 1 < 8) {
                gemm1_chunk(sm, sb, 2 * (kc + 1),     hoff,         w, lane, t, g);
                gemm1_chunk(sm, sb, 2 * (kc + 1) + 1, hoff + 10240, w, lane, t, g);
            }
        } else {
            if (kc + 1 < 8) {
                gemm1_chunk(sm, sb, 2 * (kc + 1),     hoff,         w, lane, t, g);
                gemm1_chunk(sm, sb, 2 * (kc + 1) + 1, hoff + 10240, w, lane, t, g);
            }
            gemm2_big(sm, hb0, kc, wn, lane, acc);
        }

        CP_WAIT0();
        __syncthreads();
    }

    float* o = out + (size_t)es * BN * DXN;
    #pragma unroll
    for (int mf = 0; mf < 2; ++mf) {
        const int ra = row0 + mf * 16 + g;
        const int rb = ra + 8;
        #pragma unroll
        for (int nf = 0; nf < 8; ++nf) {
            const int cb = wn * 64 + nf * 8 + t * 2;
            float2 bb = *reinterpret_cast<const float2*>(bd2 + cb);
            float2 o0 = make_float2(acc[mf][nf][0] + bb.x, acc[mf][nf][1] + bb.y);
            float2 o1 = make_float2(acc[mf][nf][2] + bb.x, acc[mf][nf][3] + bb.y);
            *reinterpret_cast<float2*>(o + (size_t)ra * DXN + cb) = o0;
            *reinterpret_cast<float2*>(o + (size_t)rb * DXN + cb) = o1;
        }
    }
}

// ===================== flow kernel (round-12 form: 1 thread per row) ==========
__global__ __launch_bounds__(256)
void flow_kernel(const float* __restrict__ e1, const float* __restrict__ e2,
                 const float* __restrict__ adj,
                 const float* __restrict__ W1, const float* __restrict__ b1,
                 const float* __restrict__ W2, const float* __restrict__ b2,
                 const float* __restrict__ W3, const float* __restrict__ b3)
{
    __shared__ float Ms[DZ * DZ];
    __shared__ float W1m[DZ * PHN * DZ];
    __shared__ float W2s[DZ * PHN * PHN];
    __shared__ float b1s[DZ * PHN];
    __shared__ float b2s[DZ * PHN];
    __shared__ float W3s[DZ * 2 * PHN];
    __shared__ float b3s[DZ * 2];
    __shared__ float red[DZ];
    __shared__ float rede1;

    const int tid = threadIdx.x;

    for (int idx = tid; idx < DZ * DZ; idx += 256) {
        int i = idx >> 5, j = idx & 31;
        float v = 0.0f;
        if (j < i)      v = 1.0f / (1.0f + expf(-adj[j * DZ + i]));
        else if (j > i) v = 1.0f - 1.0f / (1.0f + expf(-adj[i * DZ + j]));
        Ms[idx] = v;
    }
    for (int idx = tid; idx < DZ * PHN; idx += 256) { b1s[idx] = b1[idx]; b2s[idx] = b2[idx]; }
    for (int idx = tid; idx < DZ * PHN * PHN; idx += 256) W2s[idx] = W2[idx];
    for (int idx = tid; idx < DZ * 2 * PHN; idx += 256) {
        int n = idx / (2 * PHN); int rem = idx - n * 2 * PHN;
        W3s[idx] = W3[n * DZ * PHN + rem];
    }
    for (int idx = tid; idx < DZ * 2; idx += 256)
        b3s[idx] = b3[(idx >> 1) * DZ + (idx & 1)];
    if (tid < DZ) red[tid] = 0.0f;
    if (tid == 0) rede1 = 0.0f;
    __syncthreads();
    for (int idx = tid; idx < DZ * PHN * DZ; idx += 256) {
        int n = idx / (PHN * DZ);
        int d = idx & (DZ - 1);
        W1m[idx] = Ms[n * DZ + d] * W1[idx];
    }
    __syncthreads();

    const int b = blockIdx.x * 256 + tid;
    float x[DZ];
    float se1 = 0.0f;
    #pragma unroll
    for (int q = 0; q < 8; ++q) {
        float4 v = *reinterpret_cast<const float4*>(e1 + (size_t)b * DZ + 4 * q);
        x[4*q] = v.x; x[4*q+1] = v.y; x[4*q+2] = v.z; x[4*q+3] = v.w;
        se1 += v.x*v.x + v.y*v.y + v.z*v.z + v.w*v.w;
    }
    se1 *= -0.5f;

    #pragma unroll 1
    for (int n = 0; n < DZ; ++n) {
        const float* w1 = W1m + n * PHN * DZ;
        float h1[PHN];
        #pragma unroll
        for (int k = 0; k < PHN; ++k) {
            const float4* wv = reinterpret_cast<const float4*>(w1 + k * DZ);
            float s = b1s[n * PHN + k];
            #pragma unroll
            for (int q = 0; q < 8; ++q) {
                float4 v = wv[q];
                s += x[4*q] * v.x + x[4*q+1] * v.y + x[4*q+2] * v.z + x[4*q+3] * v.w;
            }
            h1[k] = fmaxf(s, 0.0f);
        }
        const float* w2 = W2s + n * PHN * PHN;
        float h2[PHN];
        #pragma unroll
        for (int m = 0; m < PHN; ++m) {
            float s = b2s[n * PHN + m];
            #pragma unroll
            for (int k = 0; k < PHN; ++k) s += h1[k] * w2[m * PHN + k];
            h2[m] = fmaxf(s, 0.0f);
        }
        const float* w3 = W3s + n * 2 * PHN;
        float shift = b3s[2 * n], lsc = b3s[2 * n + 1];
        #pragma unroll
        for (int m = 0; m < PHN; ++m) { shift += h2[m] * w3[m]; lsc += h2[m] * w3[PHN + m]; }

        float z = (e2[(size_t)b * DZ + n] - shift) * expf(-lsc);
        float c = -0.5f * z * z - lsc;
        #pragma unroll
        for (int o = 16; o; o >>= 1) c += __shfl_xor_sync(0xffffffffu, c, o);
        if ((tid & 31) == 0) atomicAdd(&red[n], c);
    }

    #pragma unroll
    for (int o = 16; o; o >>= 1) se1 += __shfl_xor_sync(0xffffffffu, se1, o);
    if ((tid & 31) == 0) atomicAdd(&rede1, se1);
    __syncthreads();
    if (tid < DZ) atomicAdd(&g_per_node[tid], red[tid]);
    if (tid == 0) atomicAdd(&g_sum_e1, rede1);
}

// ===================== small kernels =====================
__global__ void init_kernel() {
    int t = threadIdx.x;
    if (t < DZ) g_per_node[t] = 0.0f;
    if (t == DZ) { g_sum_e1 = 0.0f; g_active_mask = 0; }
}

__global__ void active_kernel(const int* __restrict__ itv) {
    const int n4 = (BN * (DZ + 1)) / 4;
    unsigned mask = 0;
    const int stride = gridDim.x * blockDim.x;
    for (int i = blockIdx.x * blockDim.x + threadIdx.x; i < n4; i += stride) {
        int4 v = reinterpret_cast<const int4*>(itv)[i];
        int c0 = (4 * i) % 33;
        int c1 = (c0 + 1 == 33) ? 0 : c0 + 1;
        int c2 = (c1 + 1 == 33) ? 0 : c1 + 1;
        int c3 = (c2 + 1 == 33) ? 0 : c2 + 1;
        if (v.x && c0) mask |= 1u << (c0 - 1);
        if (v.y && c1) mask |= 1u << (c1 - 1);
        if (v.z && c2) mask |= 1u << (c2 - 1);
        if (v.w && c3) mask |= 1u << (c3 - 1);
    }
    mask = __reduce_or_sync(0xffffffffu, mask);
    if ((threadIdx.x & 31) == 0 && mask) atomicOr(&g_active_mask, (int)mask);
}

__global__ void finalize_kernel(float* __restrict__ out) {
    if (threadIdx.x == 0 && blockIdx.x == 0) {
        float lp = g_sum_e1 - 0.5f * LOG2PI * (float)((long long)BN * DZ);
        int msk = g_active_mask;
        #pragma unroll
        for (int n = 0; n < DZ; ++n)
            if ((msk >> n) & 1) lp += g_per_node[n] - 0.5f * LOG2PI * (float)BN;
        lp -= logf((float)(DZ + 1)) * (float)BN;
        out[(size_t)2 * BN * DXN] = lp;
    }
}

// ===================== kernel_launch (forked-stream overlap) =====================
extern "C" void kernel_launch(void* const* d_in, const int* in_sizes, int n_in,
                              void* d_out, int out_size)
{
    (void)in_sizes; (void)n_in; (void)out_size;
    const float* e1  = (const float*)d_in[0];
    const float* e2  = (const float*)d_in[1];
    const float* adj = (const float*)d_in[2];
    const float* W1  = (const float*)d_in[3];
    const float* b1  = (const float*)d_in[4];
    const float* W2  = (const float*)d_in[5];
    const float* b2  = (const float*)d_in[6];
    const float* W3  = (const float*)d_in[7];
    const float* b3  = (const float*)d_in[8];
    const float* Wd1 = (const float*)d_in[9];
    const float* bd1 = (const float*)d_in[10];
    const float* Wd2 = (const float*)d_in[11];
    const float* bd2 = (const float*)d_in[12];
    const int*   itv = (const int*)d_in[13];
    float* out = (float*)d_out;

    // lazily-created side stream + fork/join events (host objects only; no
    // device allocation; identical work on every call)
    static cudaStream_t s2 = nullptr;
    static cudaEvent_t evFork = nullptr, evJoin = nullptr;
    if (s2 == nullptr) {
        cudaStreamCreateWithFlags(&s2, cudaStreamNonBlocking);
        cudaEventCreateWithFlags(&evFork, cudaEventDisableTiming);
        cudaEventCreateWithFlags(&evJoin, cudaEventDisableTiming);
        cudaFuncSetAttribute(dec_mma, cudaFuncAttributeMaxDynamicSharedMemorySize, SMEM_TOT);
    }

    // main stream: init -> fork
    init_kernel<<<1, 64>>>();
    cudaEventRecord(evFork, 0);
    cudaStreamWaitEvent(s2, evFork, 0);

    // side stream: flow + active (independent of decoder weights/output)
    flow_kernel<<<BN / 256, 256, 0, s2>>>(e1, e2, adj, W1, b1, W2, b2, W3, b3);
    active_kernel<<<264, 256, 0, s2>>>(itv);
    cudaEventRecord(evJoin, s2);

    // main stream: preps + decoder
    prep_w1f<<<16, 256>>>(Wd1);
    prep_w2f<<<64, 256>>>(Wd2);
    dim3 dg(BN / 128, 2);
    dec_mma<<<dg, 512, SMEM_TOT>>>(e1, e2, bd1, bd2, out);

    // join, then finalize
    cudaStreamWaitEvent(0, evJoin, 0);
    finalize_kernel<<<1, 32>>>(out);
}

// round 16
// speedup vs baseline: 1.7574x; 1.0351x over previous
#include <cuda_runtime.h>
#include <cuda_fp16.h>
#include <math.h>
#include <stdint.h>

#define BN   65536
#define DZ   32
#define HIDN 512
#define DXN  256
#define PHN  5
#define LOG2PI 1.8378770664093453f

typedef unsigned long long ull;

// ===================== helpers =====================
__device__ __forceinline__ uint32_t smem_u32(const void* p) {
    uint32_t a;
    asm("{ .reg .u64 t; cvta.to.shared.u64 t, %1; cvt.u32.u64 %0, t; }" : "=r"(a) : "l"(p));
    return a;
}

__device__ __forceinline__ void mma_f16(float& d0, float& d1, float& d2, float& d3,
                                        uint32_t a0, uint32_t a1, uint32_t a2, uint32_t a3,
                                        uint32_t b0, uint32_t b1) {
    asm volatile("mma.sync.aligned.m16n8k16.row.col.f32.f16.f16.f32 "
                 "{%0,%1,%2,%3},{%4,%5,%6,%7},{%8,%9},{%0,%1,%2,%3};"
                 : "+f"(d0), "+f"(d1), "+f"(d2), "+f"(d3)
                 : "r"(a0), "r"(a1), "r"(a2), "r"(a3), "r"(b0), "r"(b1));
}

__device__ __forceinline__ void split2h(float x0, float x1, uint32_t& hi, uint32_t& lo) {
    asm("cvt.rn.f16x2.f32 %0, %1, %2;" : "=r"(hi) : "f"(x1), "f"(x0));
    __half2 h = *reinterpret_cast<__half2*>(&hi);
    float f0 = __half2float(__low2half(h));
    float f1 = __half2float(__high2half(h));
    float l0 = x0 - f0, l1 = x1 - f1;
    asm("cvt.rn.f16x2.f32 %0, %1, %2;" : "=r"(lo) : "f"(l1), "f"(l0));
}

__device__ __forceinline__ uint32_t pack2h(float x0, float x1) {
    uint32_t r;
    asm("cvt.rn.f16x2.f32 %0, %1, %2;" : "=r"(r) : "f"(x1), "f"(x0));
    return r;
}

__device__ __forceinline__ void ldmx4(uint32_t* r, uint32_t addr) {
    asm volatile("ldmatrix.sync.aligned.m8n8.x4.shared.b16 {%0,%1,%2,%3}, [%4];"
                 : "=r"(r[0]), "=r"(r[1]), "=r"(r[2]), "=r"(r[3]) : "r"(addr));
}

__device__ __forceinline__ void cp16(uint32_t dst, const void* src) {
    asm volatile("cp.async.cg.shared.global [%0], [%1], 16;" :: "r"(dst), "l"(src));
}
#define CP_COMMIT() asm volatile("cp.async.commit_group;" ::: "memory")
#define CP_WAIT0()  asm volatile("cp.async.wait_group 0;" ::: "memory")

// ---------- f32x2 packed helpers ----------
__device__ __forceinline__ ull pk2(float lo, float hi) {
    ull r; asm("mov.b64 %0, {%1, %2};" : "=l"(r) : "f"(lo), "f"(hi)); return r;
}
__device__ __forceinline__ float2 upk2(ull v) {
    float2 r; asm("mov.b64 {%0, %1}, %2;" : "=f"(r.x), "=f"(r.y) : "l"(v)); return r;
}
__device__ __forceinline__ void fma2(ull& d, ull a, ull b) {
    asm("fma.rn.f32x2 %0, %1, %2, %0;" : "+l"(d) : "l"(a), "l"(b));
}
__device__ __forceinline__ ull relu2(ull v) {
    float2 f = upk2(v);
    return pk2(fmaxf(f.x, 0.0f), fmaxf(f.y, 0.0f));
}

// ===================== global scratch =====================
__device__ float g_per_node[DZ];
__device__ float g_sum_e1;
__device__ int   g_active_mask;

__device__ uint32_t gW1f[16 * 1024];     // 64 KB  fp16 hi/lo fragments
__device__ uint32_t gW2f[16 * 4096];     // 256 KB fp16 single fragments

// ===================== prep kernels =====================
__global__ void prep_w1f(const float* __restrict__ Wd1) {
    int idx = blockIdx.x * 256 + threadIdx.x;
    if (idx >= 4096) return;
    int lane = idx & 31, nt = (idx >> 5) & 3, kt = (idx >> 7) & 1, kc = idx >> 8;
    int t = lane & 3, g = lane >> 2;
    int k0 = kt * 16 + t * 2;
    int n  = kc * 32 + nt * 8 + g;
    float b00 = Wd1[(k0    ) * HIDN + n];
    float b01 = Wd1[(k0 + 1) * HIDN + n];
    float b10 = Wd1[(k0 + 8) * HIDN + n];
    float b11 = Wd1[(k0 + 9) * HIDN + n];
    uint32_t hi0, lo0, hi1, lo1;
    split2h(b00, b01, hi0, lo0);
    split2h(b10, b11, hi1, lo1);
    uint32_t* p = gW1f + (((kc * 2 + kt) * 4 + nt) * 32 + lane) * 4;
    p[0] = hi0; p[1] = hi1; p[2] = lo0; p[3] = lo1;
}

__global__ void prep_w2f(const float* __restrict__ Wd2) {
    int idx = blockIdx.x * 256 + threadIdx.x;
    if (idx >= 16384) return;
    int lane = idx & 31, nf = (idx >> 5) & 31, kc = idx >> 10;
    int t = lane & 3, g = lane >> 2;
    int k0 = kc * 32 + t * 2;
    int n  = nf * 8 + g;
    uint32_t q[4];
    #pragma unroll
    for (int j = 0; j < 4; ++j) {
        int kk = k0 + j * 8;
        q[j] = pack2h(Wd2[kk * DXN + n], Wd2[(kk + 1) * DXN + n]);
    }
    uint32_t* p = gW2f + ((kc * 32 + nf) * 32 + lane) * 4;
    p[0] = q[0]; p[1] = q[1]; p[2] = q[2]; p[3] = q[3];
}

// ===================== fused decoder (unchanged from R12/R14) =====================
#define SMEM_W2   0
#define SMEM_W1   65536
#define SMEM_BD1  131072
#define SMEM_EH   133120
#define SMEM_EL   143360
#define SMEM_H    153600
#define SMEM_TOT  194560

__device__ __forceinline__ void gemm1_chunk(char* sm, uint32_t sb, int kcn, uint32_t hoff,
                                            int w, int lane, int t, int g)
{
    const int mt8 = w >> 1, nh = w & 1;
    const char* w1s = sm + SMEM_W1 + kcn * 4096;
    const float* bd1s = (const float*)(sm + SMEM_BD1) + kcn * 32;
    char* hbase = sm + hoff;

    const uint32_t arow = (uint32_t)((mt8 * 16 + (lane & 15)) * 80 + (lane >> 4) * 16);
    const uint32_t ehb = sb + SMEM_EH + arow;
    const uint32_t elb = sb + SMEM_EL + arow;

    float ha[2][4];
    #pragma unroll
    for (int ntl = 0; ntl < 2; ++ntl)
        #pragma unroll
        for (int r = 0; r < 4; ++r) ha[ntl][r] = 0.0f;

    #pragma unroll
    for (int kt = 0; kt < 2; ++kt) {
        uint32_t eh[4], el[4];
        ldmx4(eh, ehb + kt * 32);
        ldmx4(el, elb + kt * 32);
        #pragma unroll
        for (int ntl = 0; ntl < 2; ++ntl) {
            const int ntg = nh * 2 + ntl;
            uint4 bf = *reinterpret_cast<const uint4*>(
                w1s + (kt * 4 + ntg) * 512 + lane * 16);
            mma_f16(ha[ntl][0], ha[ntl][1], ha[ntl][2], ha[ntl][3],
                    eh[0], eh[1], eh[2], eh[3], bf.x, bf.y);
            mma_f16(ha[ntl][0], ha[ntl][1], ha[ntl][2], ha[ntl][3],
                    eh[0], eh[1], eh[2], eh[3], bf.z, bf.w);
            mma_f16(ha[ntl][0], ha[ntl][1], ha[ntl][2], ha[ntl][3],
                    el[0], el[1], el[2], el[3], bf.x, bf.y);
        }
    }

    const int rowA = mt8 * 16 + g;
    #pragma unroll
    for (int ntl = 0; ntl < 2; ++ntl) {
        const int col = nh * 16 + ntl * 8 + t * 2;
        float2 bb = *reinterpret_cast<const float2*>(bd1s + col);
        float c0 = fmaxf(ha[ntl][0] + bb.x, 0.0f);
        float c1 = fmaxf(ha[ntl][1] + bb.y, 0.0f);
        float c2 = fmaxf(ha[ntl][2] + bb.x, 0.0f);
        float c3 = fmaxf(ha[ntl][3] + bb.y, 0.0f);
        const uint32_t offA = (uint32_t)(rowA * 80 + (col >> 1) * 4);
        *reinterpret_cast<uint32_t*>(hbase + offA)       = pack2h(c0, c1);
        *reinterpret_cast<uint32_t*>(hbase + offA + 640) = pack2h(c2, c3);
    }
}

__device__ __forceinline__ void gemm2_big(const char* sm, uint32_t hb0, int kc,
                                          int wn, int lane, float (&acc)[2][8][4])
{
    const char* w2b = sm + SMEM_W2 + (kc & 1) * 32768;
    const uint32_t hhb = hb0 + (kc & 1) * 20480;
    #pragma unroll
    for (int s = 0; s < 2; ++s) {
        const char* w2s = w2b + s * 16384;
        const uint32_t hh = hhb + s * 10240;
        uint32_t hf[2][2][4];
        #pragma unroll
        for (int mf = 0; mf < 2; ++mf) {
            ldmx4(hf[mf][0], hh + mf * (16 * 80));
            ldmx4(hf[mf][1], hh + mf * (16 * 80) + 32);
        }
        #pragma unroll
        for (int nf = 0; nf < 8; ++nf) {
            uint4 bf = *reinterpret_cast<const uint4*>(
                w2s + (wn * 8 + nf) * 512 + lane * 16);
            #pragma unroll
            for (int mf = 0; mf < 2; ++mf) {
                mma_f16(acc[mf][nf][0], acc[mf][nf][1], acc[mf][nf][2], acc[mf][nf][3],
                        hf[mf][0][0], hf[mf][0][1], hf[mf][0][2], hf[mf][0][3], bf.x, bf.y);
                mma_f16(acc[mf][nf][0], acc[mf][nf][1], acc[mf][nf][2], acc[mf][nf][3],
                        hf[mf][1][0], hf[mf][1][1], hf[mf][1][2], hf[mf][1][3], bf.z, bf.w);
            }
        }
    }
}

__global__ __launch_bounds__(512, 1)
void dec_mma(const float* __restrict__ e1, const float* __restrict__ e2,
             const float* __restrict__ bd1, const float* __restrict__ bd2,
             float* __restrict__ out)
{
    extern __shared__ char sm[];
    const uint32_t sb = smem_u32(sm);
    const int tid = threadIdx.x, lane = tid & 31, w = tid >> 5;
    const int t = lane & 3, g = lane >> 2;
    const int mt = blockIdx.x, es = blockIdx.y;
    const float* E = es ? e2 : e1;
    const int wm = w & 3, wn = w >> 2;
    const int row0 = mt * 128 + wm * 32;

    ((float*)(sm + SMEM_BD1))[tid] = bd1[tid];

    {
        const int row = tid >> 2, seg = tid & 3;
        const float4* src = reinterpret_cast<const float4*>(
            E + (size_t)(mt * 128 + row) * DZ + seg * 8);
        float4 v0 = src[0], v1 = src[1];
        uint32_t hibuf[4], lobuf[4];
        split2h(v0.x, v0.y, hibuf[0], lobuf[0]);
        split2h(v0.z, v0.w, hibuf[1], lobuf[1]);
        split2h(v1.x, v1.y, hibuf[2], lobuf[2]);
        split2h(v1.z, v1.w, hibuf[3], lobuf[3]);
        *reinterpret_cast<uint4*>(sm + SMEM_EH + row * 80 + seg * 16) =
            *reinterpret_cast<uint4*>(hibuf);
        *reinterpret_cast<uint4*>(sm + SMEM_EL + row * 80 + seg * 16) =
            *reinterpret_cast<uint4*>(lobuf);
    }

    {
        const uint4* g1 = reinterpret_cast<const uint4*>(gW1f);
        #pragma unroll
        for (int q = 0; q < 8; ++q)
            cp16(sb + SMEM_W1 + (tid + 512 * q) * 16, g1 + tid + 512 * q);
        const uint4* g2 = reinterpret_cast<const uint4*>(gW2f);
        #pragma unroll
        for (int q = 0; q < 4; ++q)
            cp16(sb + SMEM_W2 + (tid + 512 * q) * 16, g2 + tid + 512 * q);
        CP_COMMIT();
    }

    float acc[2][8][4];
    #pragma unroll
    for (int mf = 0; mf < 2; ++mf)
        #pragma unroll
        for (int nf = 0; nf < 8; ++nf)
            #pragma unroll
            for (int r = 0; r < 4; ++r) acc[mf][nf][r] = 0.0f;

    const uint32_t lm_off = (uint32_t)((wm * 32 + (lane & 15)) * 80 + (lane >> 4) * 16);
    const uint32_t hb0 = sb + SMEM_H + lm_off;

    CP_WAIT0();
    __syncthreads();
    gemm1_chunk(sm, sb, 0, SMEM_H,         w, lane, t, g);
    gemm1_chunk(sm, sb, 1, SMEM_H + 10240, w, lane, t, g);
    __syncthreads();

    for (int kc = 0; kc < 8; ++kc) {
        if (kc + 1 < 8) {
            const uint4* g2 = reinterpret_cast<const uint4*>(gW2f + (kc + 1) * 8192);
            const uint32_t dst = sb + SMEM_W2 + ((kc + 1) & 1) * 32768;
            #pragma unroll
            for (int q = 0; q < 4; ++q)
                cp16(dst + (tid + 512 * q) * 16, g2 + tid + 512 * q);
            CP_COMMIT();
        }

        const uint32_t hoff = SMEM_H + ((kc + 1) & 1) * 20480;
        if (w & 1) {
            gemm2_big(sm, hb0, kc, wn, lane, acc);
            if (kc + 1 < 8) {
                gemm1_chunk(sm, sb, 2 * (kc + 1),     hoff,         w, lane, t, g);
                gemm1_chunk(sm, sb, 2 * (kc + 1) + 1, hoff + 10240, w, lane, t, g);
            }
        } else {
            if (kc + 1 < 8) {
                gemm1_chunk(sm, sb, 2 * (kc + 1),     hoff,         w, lane, t, g);
                gemm1_chunk(sm, sb, 2 * (kc + 1) + 1, hoff + 10240, w, lane, t, g);
            }
            gemm2_big(sm, hb0, kc, wn, lane, acc);
        }

        CP_WAIT0();
        __syncthreads();
    }

    float* o = out + (size_t)es * BN * DXN;
    #pragma unroll
    for (int mf = 0; mf < 2; ++mf) {
        const int ra = row0 + mf * 16 + g;
        const int rb = ra + 8;
        #pragma unroll
        for (int nf = 0; nf < 8; ++nf) {
            const int cb = wn * 64 + nf * 8 + t * 2;
            float2 bb = *reinterpret_cast<const float2*>(bd2 + cb);
            float2 o0 = make_float2(acc[mf][nf][0] + bb.x, acc[mf][nf][1] + bb.y);
            float2 o1 = make_float2(acc[mf][nf][2] + bb.x, acc[mf][nf][3] + bb.y);
            *reinterpret_cast<float2*>(o + (size_t)ra * DXN + cb) = o0;
            *reinterpret_cast<float2*>(o + (size_t)rb * DXN + cb) = o1;
        }
    }
}

// ===================== flow kernel: f32x2, 2 rows/thread, splatted weights ====
#define FL_W1  0        /* 5120 ull = 40960 */
#define FL_W2  40960    /* 800 ull  = 6400  */
#define FL_W3  47360    /* 320 ull  = 2560  */
#define FL_B1  49920    /* 160 f */
#define FL_B2  50560    /* 160 f */
#define FL_B3  51200    /* 64 f  */
#define FL_MS  51456    /* 1024 f = 4096 */
#define FL_RED 55552    /* 33 f  */
#define FL_TOT 55808

__global__ __launch_bounds__(256)
void flow_kernel(const float* __restrict__ e1, const float* __restrict__ e2,
                 const float* __restrict__ adj,
                 const float* __restrict__ W1, const float* __restrict__ b1,
                 const float* __restrict__ W2, const float* __restrict__ b2,
                 const float* __restrict__ W3, const float* __restrict__ b3)
{
    extern __shared__ char fsm[];
    ull*   W1p = (ull*)(fsm + FL_W1);
    ull*   W2p = (ull*)(fsm + FL_W2);
    ull*   W3p = (ull*)(fsm + FL_W3);
    float* b1s = (float*)(fsm + FL_B1);
    float* b2s = (float*)(fsm + FL_B2);
    float* b3s = (float*)(fsm + FL_B3);
    float* Ms  = (float*)(fsm + FL_MS);
    float* red = (float*)(fsm + FL_RED);

    const int tid = threadIdx.x;

    for (int idx = tid; idx < DZ * DZ; idx += 256) {
        int i = idx >> 5, j = idx & 31;
        float v = 0.0f;
        if (j < i)      v = 1.0f / (1.0f + expf(-adj[j * DZ + i]));
        else if (j > i) v = 1.0f - 1.0f / (1.0f + expf(-adj[i * DZ + j]));
        Ms[idx] = v;
    }
    for (int idx = tid; idx < DZ * PHN; idx += 256) { b1s[idx] = b1[idx]; b2s[idx] = b2[idx]; }
    for (int idx = tid; idx < DZ * PHN * PHN; idx += 256) {
        float v = W2[idx]; W2p[idx] = pk2(v, v);
    }
    for (int idx = tid; idx < DZ * 2 * PHN; idx += 256) {
        int n = idx / (2 * PHN); int rem = idx - n * 2 * PHN;
        float v = W3[n * DZ * PHN + rem]; W3p[idx] = pk2(v, v);
    }
    for (int idx = tid; idx < DZ * 2; idx += 256)
        b3s[idx] = b3[(idx >> 1) * DZ + (idx & 1)];
    if (tid < 33) red[tid] = 0.0f;
    __syncthreads();
    for (int idx = tid; idx < DZ * PHN * DZ; idx += 256) {
        int n = idx / (PHN * DZ);
        int d = idx & (DZ - 1);
        float v = Ms[n * DZ + d] * W1[idx];
        W1p[idx] = pk2(v, v);
    }
    __syncthreads();

    const int rA = blockIdx.x * 512 + tid;
    const int rB = rA + 256;
    ull x2[DZ];
    float se1 = 0.0f;
    #pragma unroll
    for (int q = 0; q < 8; ++q) {
        float4 a = *reinterpret_cast<const float4*>(e1 + (size_t)rA * DZ + 4 * q);
        float4 b4 = *reinterpret_cast<const float4*>(e1 + (size_t)rB * DZ + 4 * q);
        x2[4*q+0] = pk2(a.x, b4.x); x2[4*q+1] = pk2(a.y, b4.y);
        x2[4*q+2] = pk2(a.z, b4.z); x2[4*q+3] = pk2(a.w, b4.w);
        se1 += a.x*a.x + a.y*a.y + a.z*a.z + a.w*a.w;
        se1 += b4.x*b4.x + b4.y*b4.y + b4.z*b4.z + b4.w*b4.w;
    }
    se1 *= -0.5f;

    #pragma unroll 1
    for (int n = 0; n < DZ; ++n) {
        const ull* w1 = W1p + n * PHN * DZ;
        ull h1p[PHN];
        #pragma unroll
        for (int k = 0; k < PHN; ++k) {
            float bb = b1s[n * PHN + k];
            ull s = pk2(bb, bb);
            const ulonglong2* wv = reinterpret_cast<const ulonglong2*>(w1 + k * DZ);
            #pragma unroll
            for (int i = 0; i < 16; ++i) {
                ulonglong2 q = wv[i];
                fma2(s, x2[2*i],   q.x);
                fma2(s, x2[2*i+1], q.y);
            }
            h1p[k] = relu2(s);
        }
        const ull* w2 = W2p + n * PHN * PHN;
        ull h2p[PHN];
        #pragma unroll
        for (int m = 0; m < PHN; ++m) {
            float bb = b2s[n * PHN + m];
            ull s = pk2(bb, bb);
            #pragma unroll
            for (int k = 0; k < PHN; ++k) fma2(s, h1p[k], w2[m * PHN + k]);
            h2p[m] = relu2(s);
        }
        const ull* w3 = W3p + n * 2 * PHN;
        float bsh = b3s[2 * n], bls = b3s[2 * n + 1];
        ull shp = pk2(bsh, bsh), lsp = pk2(bls, bls);
        #pragma unroll
        for (int m = 0; m < PHN; ++m) { fma2(shp, h2p[m], w3[m]); fma2(lsp, h2p[m], w3[PHN + m]); }

        float2 sh = upk2(shp), ls = upk2(lsp);
        float eA = e2[(size_t)rA * DZ + n];
        float eB = e2[(size_t)rB * DZ + n];
        float zA = (eA - sh.x) * expf(-ls.x);
        float zB = (eB - sh.y) * expf(-ls.y);
        float c = (-0.5f * zA * zA - ls.x) + (-0.5f * zB * zB - ls.y);
        #pragma unroll
        for (int o = 16; o; o >>= 1) c += __shfl_xor_sync(0xffffffffu, c, o);
        if ((tid & 31) == 0) atomicAdd(&red[n], c);
    }

    #pragma unroll
    for (int o = 16; o; o >>= 1) se1 += __shfl_xor_sync(0xffffffffu, se1, o);
    if ((tid & 31) == 0) atomicAdd(&red[32], se1);
    __syncthreads();
    if (tid < DZ) atomicAdd(&g_per_node[tid], red[tid]);
    if (tid == DZ) atomicAdd(&g_sum_e1, red[32]);
}

// ===================== small kernels =====================
__global__ void init_kernel() {
    int t = threadIdx.x;
    if (t < DZ) g_per_node[t] = 0.0f;
    if (t == DZ) { g_sum_e1 = 0.0f; g_active_mask = 0; }
}

__global__ void active_kernel(const int* __restrict__ itv) {
    const int n4 = (BN * (DZ + 1)) / 4;
    unsigned mask = 0;
    const int stride = gridDim.x * blockDim.x;
    for (int i = blockIdx.x * blockDim.x + threadIdx.x; i < n4; i += stride) {
        int4 v = reinterpret_cast<const int4*>(itv)[i];
        int c0 = (4 * i) % 33;
        int c1 = (c0 + 1 == 33) ? 0 : c0 + 1;
        int c2 = (c1 + 1 == 33) ? 0 : c1 + 1;
        int c3 = (c2 + 1 == 33) ? 0 : c2 + 1;
        if (v.x && c0) mask |= 1u << (c0 - 1);
        if (v.y && c1) mask |= 1u << (c1 - 1);
        if (v.z && c2) mask |= 1u << (c2 - 1);
        if (v.w && c3) mask |= 1u << (c3 - 1);
    }
    mask = __reduce_or_sync(0xffffffffu, mask);
    if ((threadIdx.x & 31) == 0 && mask) atomicOr(&g_active_mask, (int)mask);
}

__global__ void finalize_kernel(float* __restrict__ out) {
    if (threadIdx.x == 0 && blockIdx.x == 0) {
        float lp = g_sum_e1 - 0.5f * LOG2PI * (float)((long long)BN * DZ);
        int msk = g_active_mask;
        #pragma unroll
        for (int n = 0; n < DZ; ++n)
            if ((msk >> n) & 1) lp += g_per_node[n] - 0.5f * LOG2PI * (float)BN;
        lp -= logf((float)(DZ + 1)) * (float)BN;
        out[(size_t)2 * BN * DXN] = lp;
    }
}

// ===================== kernel_launch (forked-stream overlap) =====================
extern "C" void kernel_launch(void* const* d_in, const int* in_sizes, int n_in,
                              void* d_out, int out_size)
{
    (void)in_sizes; (void)n_in; (void)out_size;
    const float* e1  = (const float*)d_in[0];
    const float* e2  = (const float*)d_in[1];
    const float* adj = (const float*)d_in[2];
    const float* W1  = (const float*)d_in[3];
    const float* b1  = (const float*)d_in[4];
    const float* W2  = (const float*)d_in[5];
    const float* b2  = (const float*)d_in[6];
    const float* W3  = (const float*)d_in[7];
    const float* b3  = (const float*)d_in[8];
    const float* Wd1 = (const float*)d_in[9];
    const float* bd1 = (const float*)d_in[10];
    const float* Wd2 = (const float*)d_in[11];
    const float* bd2 = (const float*)d_in[12];
    const int*   itv = (const int*)d_in[13];
    float* out = (float*)d_out;

    static cudaStream_t s2 = nullptr;
    static cudaEvent_t evFork = nullptr, evJoin = nullptr;
    if (s2 == nullptr) {
        cudaStreamCreateWithFlags(&s2, cudaStreamNonBlocking);
        cudaEventCreateWithFlags(&evFork, cudaEventDisableTiming);
        cudaEventCreateWithFlags(&evJoin, cudaEventDisableTiming);
        cudaFuncSetAttribute(dec_mma, cudaFuncAttributeMaxDynamicSharedMemorySize, SMEM_TOT);
        cudaFuncSetAttribute(flow_kernel, cudaFuncAttributeMaxDynamicSharedMemorySize, FL_TOT);
    }

    init_kernel<<<1, 64>>>();
    cudaEventRecord(evFork, 0);
    cudaStreamWaitEvent(s2, evFork, 0);

    flow_kernel<<<BN / 512, 256, FL_TOT, s2>>>(e1, e2, adj, W1, b1, W2, b2, W3, b3);
    active_kernel<<<264, 256, 0, s2>>>(itv);
    cudaEventRecord(evJoin, s2);

    prep_w1f<<<16, 256>>>(Wd1);
    prep_w2f<<<64, 256>>>(Wd2);
    dim3 dg(BN / 128, 2);
    dec_mma<<<dg, 512, SMEM_TOT>>>(e1, e2, bd1, bd2, out);

    cudaStreamWaitEvent(0, evJoin, 0);
    finalize_kernel<<<1, 32>>>(out);
}

// round 17
// speedup vs baseline: 1.7974x; 1.0227x over previous
#include <cuda_runtime.h>
#include <cuda_fp16.h>
#include <math.h>
#include <stdint.h>

#define BN   65536
#define DZ   32
#define HIDN 512
#define DXN  256
#define PHN  5
#define LOG2PI 1.8378770664093453f

typedef unsigned long long ull;

// ===================== helpers =====================
__device__ __forceinline__ uint32_t smem_u32(const void* p) {
    uint32_t a;
    asm("{ .reg .u64 t; cvta.to.shared.u64 t, %1; cvt.u32.u64 %0, t; }" : "=r"(a) : "l"(p));
    return a;
}

__device__ __forceinline__ void mma_f16(float& d0, float& d1, float& d2, float& d3,
                                        uint32_t a0, uint32_t a1, uint32_t a2, uint32_t a3,
                                        uint32_t b0, uint32_t b1) {
    asm volatile("mma.sync.aligned.m16n8k16.row.col.f32.f16.f16.f32 "
                 "{%0,%1,%2,%3},{%4,%5,%6,%7},{%8,%9},{%0,%1,%2,%3};"
                 : "+f"(d0), "+f"(d1), "+f"(d2), "+f"(d3)
                 : "r"(a0), "r"(a1), "r"(a2), "r"(a3), "r"(b0), "r"(b1));
}

__device__ __forceinline__ void split2h(float x0, float x1, uint32_t& hi, uint32_t& lo) {
    asm("cvt.rn.f16x2.f32 %0, %1, %2;" : "=r"(hi) : "f"(x1), "f"(x0));
    __half2 h = *reinterpret_cast<__half2*>(&hi);
    float f0 = __half2float(__low2half(h));
    float f1 = __half2float(__high2half(h));
    float l0 = x0 - f0, l1 = x1 - f1;
    asm("cvt.rn.f16x2.f32 %0, %1, %2;" : "=r"(lo) : "f"(l1), "f"(l0));
}

__device__ __forceinline__ uint32_t pack2h(float x0, float x1) {
    uint32_t r;
    asm("cvt.rn.f16x2.f32 %0, %1, %2;" : "=r"(r) : "f"(x1), "f"(x0));
    return r;
}

__device__ __forceinline__ void ldmx4(uint32_t* r, uint32_t addr) {
    asm volatile("ldmatrix.sync.aligned.m8n8.x4.shared.b16 {%0,%1,%2,%3}, [%4];"
                 : "=r"(r[0]), "=r"(r[1]), "=r"(r[2]), "=r"(r[3]) : "r"(addr));
}

__device__ __forceinline__ void cp16(uint32_t dst, const void* src) {
    asm volatile("cp.async.cg.shared.global [%0], [%1], 16;" :: "r"(dst), "l"(src));
}
#define CP_COMMIT() asm volatile("cp.async.commit_group;" ::: "memory")
#define CP_WAIT0()  asm volatile("cp.async.wait_group 0;" ::: "memory")

// ---------- f32x2 packed helpers ----------
__device__ __forceinline__ ull pk2(float lo, float hi) {
    ull r; asm("mov.b64 %0, {%1, %2};" : "=l"(r) : "f"(lo), "f"(hi)); return r;
}
__device__ __forceinline__ float2 upk2(ull v) {
    float2 r; asm("mov.b64 {%0, %1}, %2;" : "=f"(r.x), "=f"(r.y) : "l"(v)); return r;
}
__device__ __forceinline__ void fma2(ull& d, ull a, ull b) {
    asm("fma.rn.f32x2 %0, %1, %2, %0;" : "+l"(d) : "l"(a), "l"(b));
}
__device__ __forceinline__ ull relu2(ull v) {
    float2 f = upk2(v);
    return pk2(fmaxf(f.x, 0.0f), fmaxf(f.y, 0.0f));
}

// ===================== global scratch =====================
__device__ float g_per_node[DZ];
__device__ float g_sum_e1;
__device__ int   g_active_mask;

__device__ uint32_t gW1f[16 * 512];      // 32 KB  fp16 hi fragments only
__device__ uint32_t gW2f[16 * 4096];     // 256 KB fp16 single fragments

// ===================== prep kernels =====================
__global__ void prep_w1f(const float* __restrict__ Wd1) {
    int idx = blockIdx.x * 256 + threadIdx.x;
    if (idx >= 4096) return;
    int lane = idx & 31, nt = (idx >> 5) & 3, kt = (idx >> 7) & 1, kc = idx >> 8;
    int t = lane & 3, g = lane >> 2;
    int k0 = kt * 16 + t * 2;
    int n  = kc * 32 + nt * 8 + g;
    float b00 = Wd1[(k0    ) * HIDN + n];
    float b01 = Wd1[(k0 + 1) * HIDN + n];
    float b10 = Wd1[(k0 + 8) * HIDN + n];
    float b11 = Wd1[(k0 + 9) * HIDN + n];
    uint32_t* p = gW1f + (((kc * 2 + kt) * 4 + nt) * 32 + lane) * 2;
    p[0] = pack2h(b00, b01);
    p[1] = pack2h(b10, b11);
}

__global__ void prep_w2f(const float* __restrict__ Wd2) {
    int idx = blockIdx.x * 256 + threadIdx.x;
    if (idx >= 16384) return;
    int lane = idx & 31, nf = (idx >> 5) & 31, kc = idx >> 10;
    int t = lane & 3, g = lane >> 2;
    int k0 = kc * 32 + t * 2;
    int n  = nf * 8 + g;
    uint32_t q[4];
    #pragma unroll
    for (int j = 0; j < 4; ++j) {
        int kk = k0 + j * 8;
        q[j] = pack2h(Wd2[kk * DXN + n], Wd2[(kk + 1) * DXN + n]);
    }
    uint32_t* p = gW2f + ((kc * 32 + nf) * 32 + lane) * 4;
    p[0] = q[0]; p[1] = q[1]; p[2] = q[2]; p[3] = q[3];
}

// ===================== fused decoder =====================
#define SMEM_W2   0                      /* 2 x 32768 */
#define SMEM_W1   65536                  /* 32768 (hi only) */
#define SMEM_BD1  98304                  /* 2048 */
#define SMEM_EH   100352                 /* 10240 */
#define SMEM_EL   110592                 /* 10240 */
#define SMEM_H    120832                 /* 2 x 20480 */
#define SMEM_TOT  161792

// GEMM1 (2-term fp16: (Eh+El)·W1h = E·W1h) for sub-chunk kcn -> H at hoff.
__device__ __forceinline__ void gemm1_chunk(char* sm, uint32_t sb, int kcn, uint32_t hoff,
                                            int w, int lane, int t, int g)
{
    const int mt8 = w >> 1, nh = w & 1;
    const char* w1s = sm + SMEM_W1 + kcn * 2048;
    const float* bd1s = (const float*)(sm + SMEM_BD1) + kcn * 32;
    char* hbase = sm + hoff;

    const uint32_t arow = (uint32_t)((mt8 * 16 + (lane & 15)) * 80 + (lane >> 4) * 16);
    const uint32_t ehb = sb + SMEM_EH + arow;
    const uint32_t elb = sb + SMEM_EL + arow;

    float ha[2][4];
    #pragma unroll
    for (int ntl = 0; ntl < 2; ++ntl)
        #pragma unroll
        for (int r = 0; r < 4; ++r) ha[ntl][r] = 0.0f;

    #pragma unroll
    for (int kt = 0; kt < 2; ++kt) {
        uint32_t eh[4], el[4];
        ldmx4(eh, ehb + kt * 32);
        ldmx4(el, elb + kt * 32);
        #pragma unroll
        for (int ntl = 0; ntl < 2; ++ntl) {
            const int ntg = nh * 2 + ntl;
            uint2 bf = *reinterpret_cast<const uint2*>(
                w1s + (kt * 4 + ntg) * 256 + lane * 8);
            mma_f16(ha[ntl][0], ha[ntl][1], ha[ntl][2], ha[ntl][3],
                    eh[0], eh[1], eh[2], eh[3], bf.x, bf.y);
            mma_f16(ha[ntl][0], ha[ntl][1], ha[ntl][2], ha[ntl][3],
                    el[0], el[1], el[2], el[3], bf.x, bf.y);
        }
    }

    const int rowA = mt8 * 16 + g;
    #pragma unroll
    for (int ntl = 0; ntl < 2; ++ntl) {
        const int col = nh * 16 + ntl * 8 + t * 2;
        float2 bb = *reinterpret_cast<const float2*>(bd1s + col);
        float c0 = fmaxf(ha[ntl][0] + bb.x, 0.0f);
        float c1 = fmaxf(ha[ntl][1] + bb.y, 0.0f);
        float c2 = fmaxf(ha[ntl][2] + bb.x, 0.0f);
        float c3 = fmaxf(ha[ntl][3] + bb.y, 0.0f);
        const uint32_t offA = (uint32_t)(rowA * 80 + (col >> 1) * 4);
        *reinterpret_cast<uint32_t*>(hbase + offA)       = pack2h(c0, c1);
        *reinterpret_cast<uint32_t*>(hbase + offA + 640) = pack2h(c2, c3);
    }
}

// GEMM2: s-outer, B fragment loaded ONCE per sub-chunk (both mf share it).
__device__ __forceinline__ void gemm2_big(const char* sm, uint32_t hb0, int kc,
                                          int wn, int lane, float (&acc)[2][8][4])
{
    const char* w2b = sm + SMEM_W2 + (kc & 1) * 32768;
    const uint32_t hhb = hb0 + (kc & 1) * 20480;
    #pragma unroll
    for (int s = 0; s < 2; ++s) {
        const char* w2s = w2b + s * 16384;
        const uint32_t hh = hhb + s * 10240;
        uint32_t hf[2][2][4];
        #pragma unroll
        for (int mf = 0; mf < 2; ++mf) {
            ldmx4(hf[mf][0], hh + mf * (16 * 80));
            ldmx4(hf[mf][1], hh + mf * (16 * 80) + 32);
        }
        #pragma unroll
        for (int nf = 0; nf < 8; ++nf) {
            uint4 bf = *reinterpret_cast<const uint4*>(
                w2s + (wn * 8 + nf) * 512 + lane * 16);
            #pragma unroll
            for (int mf = 0; mf < 2; ++mf) {
                mma_f16(acc[mf][nf][0], acc[mf][nf][1], acc[mf][nf][2], acc[mf][nf][3],
                        hf[mf][0][0], hf[mf][0][1], hf[mf][0][2], hf[mf][0][3], bf.x, bf.y);
                mma_f16(acc[mf][nf][0], acc[mf][nf][1], acc[mf][nf][2], acc[mf][nf][3],
                        hf[mf][1][0], hf[mf][1][1], hf[mf][1][2], hf[mf][1][3], bf.z, bf.w);
            }
        }
    }
}

__global__ __launch_bounds__(512, 1)
void dec_mma(const float* __restrict__ e1, const float* __restrict__ e2,
             const float* __restrict__ bd1, const float* __restrict__ bd2,
             float* __restrict__ out)
{
    extern __shared__ char sm[];
    const uint32_t sb = smem_u32(sm);
    const int tid = threadIdx.x, lane = tid & 31, w = tid >> 5;
    const int t = lane & 3, g = lane >> 2;
    const int mt = blockIdx.x, es = blockIdx.y;
    const float* E = es ? e2 : e1;
    const int wm = w & 3, wn = w >> 2;
    const int row0 = mt * 128 + wm * 32;

    ((float*)(sm + SMEM_BD1))[tid] = bd1[tid];

    {
        const int row = tid >> 2, seg = tid & 3;
        const float4* src = reinterpret_cast<const float4*>(
            E + (size_t)(mt * 128 + row) * DZ + seg * 8);
        float4 v0 = src[0], v1 = src[1];
        uint32_t hibuf[4], lobuf[4];
        split2h(v0.x, v0.y, hibuf[0], lobuf[0]);
        split2h(v0.z, v0.w, hibuf[1], lobuf[1]);
        split2h(v1.x, v1.y, hibuf[2], lobuf[2]);
        split2h(v1.z, v1.w, hibuf[3], lobuf[3]);
        *reinterpret_cast<uint4*>(sm + SMEM_EH + row * 80 + seg * 16) =
            *reinterpret_cast<uint4*>(hibuf);
        *reinterpret_cast<uint4*>(sm + SMEM_EL + row * 80 + seg * 16) =
            *reinterpret_cast<uint4*>(lobuf);
    }

    // preload W1-hi (32 KB) + W2 big chunk 0 (32 KB)
    {
        const uint4* g1 = reinterpret_cast<const uint4*>(gW1f);
        #pragma unroll
        for (int q = 0; q < 4; ++q)
            cp16(sb + SMEM_W1 + (tid + 512 * q) * 16, g1 + tid + 512 * q);
        const uint4* g2 = reinterpret_cast<const uint4*>(gW2f);
        #pragma unroll
        for (int q = 0; q < 4; ++q)
            cp16(sb + SMEM_W2 + (tid + 512 * q) * 16, g2 + tid + 512 * q);
        CP_COMMIT();
    }

    float acc[2][8][4];
    #pragma unroll
    for (int mf = 0; mf < 2; ++mf)
        #pragma unroll
        for (int nf = 0; nf < 8; ++nf)
            #pragma unroll
            for (int r = 0; r < 4; ++r) acc[mf][nf][r] = 0.0f;

    const uint32_t lm_off = (uint32_t)((wm * 32 + (lane & 15)) * 80 + (lane >> 4) * 16);
    const uint32_t hb0 = sb + SMEM_H + lm_off;

    CP_WAIT0();
    __syncthreads();
    gemm1_chunk(sm, sb, 0, SMEM_H,         w, lane, t, g);
    gemm1_chunk(sm, sb, 1, SMEM_H + 10240, w, lane, t, g);
    __syncthreads();

    for (int kc = 0; kc < 8; ++kc) {
        if (kc + 1 < 8) {
            const uint4* g2 = reinterpret_cast<const uint4*>(gW2f + (kc + 1) * 8192);
            const uint32_t dst = sb + SMEM_W2 + ((kc + 1) & 1) * 32768;
            #pragma unroll
            for (int q = 0; q < 4; ++q)
                cp16(dst + (tid + 512 * q) * 16, g2 + tid + 512 * q);
            CP_COMMIT();
        }

        const uint32_t hoff = SMEM_H + ((kc + 1) & 1) * 20480;
        if (w & 1) {
            gemm2_big(sm, hb0, kc, wn, lane, acc);
            if (kc + 1 < 8) {
                gemm1_chunk(sm, sb, 2 * (kc + 1),     hoff,         w, lane, t, g);
                gemm1_chunk(sm, sb, 2 * (kc + 1) + 1, hoff + 10240, w, lane, t, g);
            }
        } else {
            if (kc + 1 < 8) {
                gemm1_chunk(sm, sb, 2 * (kc + 1),     hoff,         w, lane, t, g);
                gemm1_chunk(sm, sb, 2 * (kc + 1) + 1, hoff + 10240, w, lane, t, g);
            }
            gemm2_big(sm, hb0, kc, wn, lane, acc);
        }

        CP_WAIT0();
        __syncthreads();
    }

    float* o = out + (size_t)es * BN * DXN;
    #pragma unroll
    for (int mf = 0; mf < 2; ++mf) {
        const int ra = row0 + mf * 16 + g;
        const int rb = ra + 8;
        #pragma unroll
        for (int nf = 0; nf < 8; ++nf) {
            const int cb = wn * 64 + nf * 8 + t * 2;
            float2 bb = *reinterpret_cast<const float2*>(bd2 + cb);
            float2 o0 = make_float2(acc[mf][nf][0] + bb.x, acc[mf][nf][1] + bb.y);
            float2 o1 = make_float2(acc[mf][nf][2] + bb.x, acc[mf][nf][3] + bb.y);
            *reinterpret_cast<float2*>(o + (size_t)ra * DXN + cb) = o0;
            *reinterpret_cast<float2*>(o + (size_t)rb * DXN + cb) = o1;
        }
    }
}

// ===================== flow kernel: f32x2, 2 rows/thread, splatted weights ====
#define FL_W1  0
#define FL_W2  40960
#define FL_W3  47360
#define FL_B1  49920
#define FL_B2  50560
#define FL_B3  51200
#define FL_MS  51456
#define FL_RED 55552
#define FL_TOT 55808

__global__ __launch_bounds__(256)
void flow_kernel(const float* __restrict__ e1, const float* __restrict__ e2,
                 const float* __restrict__ adj,
                 const float* __restrict__ W1, const float* __restrict__ b1,
                 const float* __restrict__ W2, const float* __restrict__ b2,
                 const float* __restrict__ W3, const float* __restrict__ b3)
{
    extern __shared__ char fsm[];
    ull*   W1p = (ull*)(fsm + FL_W1);
    ull*   W2p = (ull*)(fsm + FL_W2);
    ull*   W3p = (ull*)(fsm + FL_W3);
    float* b1s = (float*)(fsm + FL_B1);
    float* b2s = (float*)(fsm + FL_B2);
    float* b3s = (float*)(fsm + FL_B3);
    float* Ms  = (float*)(fsm + FL_MS);
    float* red = (float*)(fsm + FL_RED);

    const int tid = threadIdx.x;

    for (int idx = tid; idx < DZ * DZ; idx += 256) {
        int i = idx >> 5, j = idx & 31;
        float v = 0.0f;
        if (j < i)      v = 1.0f / (1.0f + expf(-adj[j * DZ + i]));
        else if (j > i) v = 1.0f - 1.0f / (1.0f + expf(-adj[i * DZ + j]));
        Ms[idx] = v;
    }
    for (int idx = tid; idx < DZ * PHN; idx += 256) { b1s[idx] = b1[idx]; b2s[idx] = b2[idx]; }
    for (int idx = tid; idx < DZ * PHN * PHN; idx += 256) {
        float v = W2[idx]; W2p[idx] = pk2(v, v);
    }
    for (int idx = tid; idx < DZ * 2 * PHN; idx += 256) {
        int n = idx / (2 * PHN); int rem = idx - n * 2 * PHN;
        float v = W3[n * DZ * PHN + rem]; W3p[idx] = pk2(v, v);
    }
    for (int idx = tid; idx < DZ * 2; idx += 256)
        b3s[idx] = b3[(idx >> 1) * DZ + (idx & 1)];
    if (tid < 33) red[tid] = 0.0f;
    __syncthreads();
    for (int idx = tid; idx < DZ * PHN * DZ; idx += 256) {
        int n = idx / (PHN * DZ);
        int d = idx & (DZ - 1);
        float v = Ms[n * DZ + d] * W1[idx];
        W1p[idx] = pk2(v, v);
    }
    __syncthreads();

    const int rA = blockIdx.x * 512 + tid;
    const int rB = rA + 256;
    ull x2[DZ];
    float se1 = 0.0f;
    #pragma unroll
    for (int q = 0; q < 8; ++q) {
        float4 a = *reinterpret_cast<const float4*>(e1 + (size_t)rA * DZ + 4 * q);
        float4 b4 = *reinterpret_cast<const float4*>(e1 + (size_t)rB * DZ + 4 * q);
        x2[4*q+0] = pk2(a.x, b4.x); x2[4*q+1] = pk2(a.y, b4.y);
        x2[4*q+2] = pk2(a.z, b4.z); x2[4*q+3] = pk2(a.w, b4.w);
        se1 += a.x*a.x + a.y*a.y + a.z*a.z + a.w*a.w;
        se1 += b4.x*b4.x + b4.y*b4.y + b4.z*b4.z + b4.w*b4.w;
    }
    se1 *= -0.5f;

    #pragma unroll 1
    for (int n = 0; n < DZ; ++n) {
        const ull* w1 = W1p + n * PHN * DZ;
        ull h1p[PHN];
        #pragma unroll
        for (int k = 0; k < PHN; ++k) {
            float bb = b1s[n * PHN + k];
            ull s = pk2(bb, bb);
            const ulonglong2* wv = reinterpret_cast<const ulonglong2*>(w1 + k * DZ);
            #pragma unroll
            for (int i = 0; i < 16; ++i) {
                ulonglong2 q = wv[i];
                fma2(s, x2[2*i],   q.x);
                fma2(s, x2[2*i+1], q.y);
            }
            h1p[k] = relu2(s);
        }
        const ull* w2 = W2p + n * PHN * PHN;
        ull h2p[PHN];
        #pragma unroll
        for (int m = 0; m < PHN; ++m) {
            float bb = b2s[n * PHN + m];
            ull s = pk2(bb, bb);
            #pragma unroll
            for (int k = 0; k < PHN; ++k) fma2(s, h1p[k], w2[m * PHN + k]);
            h2p[m] = relu2(s);
        }
        const ull* w3 = W3p + n * 2 * PHN;
        float bsh = b3s[2 * n], bls = b3s[2 * n + 1];
        ull shp = pk2(bsh, bsh), lsp = pk2(bls, bls);
        #pragma unroll
        for (int m = 0; m < PHN; ++m) { fma2(shp, h2p[m], w3[m]); fma2(lsp, h2p[m], w3[PHN + m]); }

        float2 sh = upk2(shp), ls = upk2(lsp);
        float eA = e2[(size_t)rA * DZ + n];
        float eB = e2[(size_t)rB * DZ + n];
        float zA = (eA - sh.x) * expf(-ls.x);
        float zB = (eB - sh.y) * expf(-ls.y);
        float c = (-0.5f * zA * zA - ls.x) + (-0.5f * zB * zB - ls.y);
        #pragma unroll
        for (int o = 16; o; o >>= 1) c += __shfl_xor_sync(0xffffffffu, c, o);
        if ((tid & 31) == 0) atomicAdd(&red[n], c);
    }

    #pragma unroll
    for (int o = 16; o; o >>= 1) se1 += __shfl_xor_sync(0xffffffffu, se1, o);
    if ((tid & 31) == 0) atomicAdd(&red[32], se1);
    __syncthreads();
    if (tid < DZ) atomicAdd(&g_per_node[tid], red[tid]);
    if (tid == DZ) atomicAdd(&g_sum_e1, red[32]);
}

// ===================== small kernels =====================
__global__ void init_kernel() {
    int t = threadIdx.x;
    if (t < DZ) g_per_node[t] = 0.0f;
    if (t == DZ) { g_sum_e1 = 0.0f; g_active_mask = 0; }
}

__global__ void active_kernel(const int* __restrict__ itv) {
    const int n4 = (BN * (DZ + 1)) / 4;
    unsigned mask = 0;
    const int stride = gridDim.x * blockDim.x;
    for (int i = blockIdx.x * blockDim.x + threadIdx.x; i < n4; i += stride) {
        int4 v = reinterpret_cast<const int4*>(itv)[i];
        int c0 = (4 * i) % 33;
        int c1 = (c0 + 1 == 33) ? 0 : c0 + 1;
        int c2 = (c1 + 1 == 33) ? 0 : c1 + 1;
        int c3 = (c2 + 1 == 33) ? 0 : c2 + 1;
        if (v.x && c0) mask |= 1u << (c0 - 1);
        if (v.y && c1) mask |= 1u << (c1 - 1);
        if (v.z && c2) mask |= 1u << (c2 - 1);
        if (v.w && c3) mask |= 1u << (c3 - 1);
    }
    mask = __reduce_or_sync(0xffffffffu, mask);
    if ((threadIdx.x & 31) == 0 && mask) atomicOr(&g_active_mask, (int)mask);
}

__global__ void finalize_kernel(float* __restrict__ out) {
    if (threadIdx.x == 0 && blockIdx.x == 0) {
        float lp = g_sum_e1 - 0.5f * LOG2PI * (float)((long long)BN * DZ);
        int msk = g_active_mask;
        #pragma unroll
        for (int n = 0; n < DZ; ++n)
            if ((msk >> n) & 1) lp += g_per_node[n] - 0.5f * LOG2PI * (float)BN;
        lp -= logf((float)(DZ + 1)) * (float)BN;
        out[(size_t)2 * BN * DXN] = lp;
    }
}

// ===================== kernel_launch (forked-stream overlap) =====================
extern "C" void kernel_launch(void* const* d_in, const int* in_sizes, int n_in,
                              void* d_out, int out_size)
{
    (void)in_sizes; (void)n_in; (void)out_size;
    const float* e1  = (const float*)d_in[0];
    const float* e2  = (const float*)d_in[1];
    const float* adj = (const float*)d_in[2];
    const float* W1  = (const float*)d_in[3];
    const float* b1  = (const float*)d_in[4];
    const float* W2  = (const float*)d_in[5];
    const float* b2  = (const float*)d_in[6];
    const float* W3  = (const float*)d_in[7];
    const float* b3  = (const float*)d_in[8];
    const float* Wd1 = (const float*)d_in[9];
    const float* bd1 = (const float*)d_in[10];
    const float* Wd2 = (const float*)d_in[11];
    const float* bd2 = (const float*)d_in[12];
    const int*   itv = (const int*)d_in[13];
    float* out = (float*)d_out;

    static cudaStream_t s2 = nullptr;
    static cudaEvent_t evFork = nullptr, evJoin = nullptr;
    if (s2 == nullptr) {
        cudaStreamCreateWithFlags(&s2, cudaStreamNonBlocking);
        cudaEventCreateWithFlags(&evFork, cudaEventDisableTiming);
        cudaEventCreateWithFlags(&evJoin, cudaEventDisableTiming);
        cudaFuncSetAttribute(dec_mma, cudaFuncAttributeMaxDynamicSharedMemorySize, SMEM_TOT);
        cudaFuncSetAttribute(flow_kernel, cudaFuncAttributeMaxDynamicSharedMemorySize, FL_TOT);
    }

    // fork immediately; side stream owns init + flow + active
    cudaEventRecord(evFork, 0);
    cudaStreamWaitEvent(s2, evFork, 0);
    init_kernel<<<1, 64, 0, s2>>>();
    flow_kernel<<<BN / 512, 256, FL_TOT, s2>>>(e1, e2, adj, W1, b1, W2, b2, W3, b3);
    active_kernel<<<264, 256, 0, s2>>>(itv);
    cudaEventRecord(evJoin, s2);

    // main stream: preps + decoder
    prep_w1f<<<16, 256>>>(Wd1);
    prep_w2f<<<64, 256>>>(Wd2);
    dim3 dg(BN / 128, 2);
    dec_mma<<<dg, 512, SMEM_TOT>>>(e1, e2, bd1, bd2, out);

    cudaStreamWaitEvent(0, evJoin, 0);
    finalize_kernel<<<1, 32>>>(out);
}